// round 10
// baseline (speedup 1.0000x reference)
#include <cuda_runtime.h>
#include <cuda_bf16.h>
#include <cstdint>
#include <cstddef>

#define N_BUS   300
#define N_GBUS  69
#define N_LINE  411
#define NB2     600
#define NG2     138
#define NL2     822
#define BATCH   32768
#define KP600   640
#define KP822   832

// ---------------- device scratch ----------------------------------------------
__device__ __nv_bfloat16 g_Ahi[BATCH * KP600], g_Alo[BATCH * KP600];   // Volt
__device__ __nv_bfloat16 g_Phi[BATCH * KP600], g_Plo[BATCH * KP600];   // n_o_l_p
__device__ __nv_bfloat16 g_Ybrhi[NL2 * KP822], g_Ybrlo[NL2 * KP822];
__device__ __nv_bfloat16 g_IMThi[NB2 * KP822], g_IMTlo[NB2 * KP822];   // IM^T
__device__ __nv_bfloat16 g_Mghi[NG2 * KP600],  g_Mglo[NG2 * KP600];    // Map_g
__device__ __nv_bfloat16 g_Whi[NL2 * KP600],   g_Wlo[NL2 * KP600];     // Ybr@IM split
__device__ float g_G[NB2 * NB2];
__device__ float g_Ibr[BATCH * NL2];
__device__ float g_stat[BATCH * NG2];
__device__ float g_colL[NB2];
__device__ float g_colg[NG2];
__device__ float g_scalar;

__device__ __forceinline__ uint32_t smem_u32(const void* p) {
    uint32_t a;
    asm("{ .reg .u64 t; cvta.to.shared.u64 t, %1; cvt.u32.u64 %0, t; }"
        : "=r"(a) : "l"(p));
    return a;
}

__device__ __forceinline__ void cp_async16(uint32_t sa, const void* gp) {
    asm volatile("cp.async.cg.shared.global [%0], [%1], 16;"
                 :: "r"(sa), "l"(gp) : "memory");
}
__device__ __forceinline__ void ldsm_x4(uint32_t* r, uint32_t addr) {
    asm volatile("ldmatrix.sync.aligned.m8n8.x4.shared.b16 {%0,%1,%2,%3}, [%4];"
                 : "=r"(r[0]), "=r"(r[1]), "=r"(r[2]), "=r"(r[3]) : "r"(addr));
}
__device__ __forceinline__ void ldsm_x2(uint32_t* r, uint32_t addr) {
    asm volatile("ldmatrix.sync.aligned.m8n8.x2.shared.b16 {%0,%1}, [%2];"
                 : "=r"(r[0]), "=r"(r[1]) : "r"(addr));
}
__device__ __forceinline__ void ldsm_x4_t(uint32_t* r, uint32_t addr) {
    asm volatile("ldmatrix.sync.aligned.m8n8.x4.trans.shared.b16 {%0,%1,%2,%3}, [%4];"
                 : "=r"(r[0]), "=r"(r[1]), "=r"(r[2]), "=r"(r[3]) : "r"(addr));
}
__device__ __forceinline__ void ldsm_x2_t(uint32_t* r, uint32_t addr) {
    asm volatile("ldmatrix.sync.aligned.m8n8.x2.trans.shared.b16 {%0,%1}, [%2];"
                 : "=r"(r[0]), "=r"(r[1]) : "r"(addr));
}
__device__ __forceinline__ void mma_bf16(float* d, const uint32_t* a, const uint32_t* b) {
    asm volatile(
        "mma.sync.aligned.m16n8k16.row.col.f32.bf16.bf16.f32 "
        "{%0,%1,%2,%3}, {%4,%5,%6,%7}, {%8,%9}, {%0,%1,%2,%3};"
        : "+f"(d[0]), "+f"(d[1]), "+f"(d[2]), "+f"(d[3])
        : "r"(a[0]), "r"(a[1]), "r"(a[2]), "r"(a[3]), "r"(b[0]), "r"(b[1]));
}

// =================== NT GEMM (A row-major [M,K], B row-major [N,K]) ===========
// nPass: 3 = Ahi*Bhi + Ahi*Blo + Alo*Bhi ; 2 = Ahi*Bhi + Ahi*Blo ; 1 = Ahi*Bhi
// Triple-buffered cp.async pipeline, ONE __syncthreads per K-stage.
#define LDSB 80
#define TILE_BYTES (128 * LDSB)
#define STG_BYTES  (4 * TILE_BYTES)
#define SMEM_DYN   (3 * STG_BYTES)       // 122880

__device__ __forceinline__ void stage_load(
    uint32_t sbase,
    const __nv_bfloat16* __restrict__ Ahi, const __nv_bfloat16* __restrict__ Alo,
    const __nv_bfloat16* __restrict__ Bhi, const __nv_bfloat16* __restrict__ Blo,
    int bm, int bn, int M, int N, int Kld, int k0, int tid, int nPass)
{
#pragma unroll
    for (int t = 0; t < 8; t++) {
        int idx = tid + t * 256;
        int arr = idx >> 9;
        if ((arr == 1 && nPass < 3) || (arr == 3 && nPass < 2)) continue;
        int c   = idx & 511;
        int row = c >> 2, seg = c & 3;
        const __nv_bfloat16* src = (arr == 0) ? Ahi : (arr == 1) ? Alo
                                 : (arr == 2) ? Bhi : Blo;
        int base = (arr < 2) ? bm : bn;
        int lim  = (arr < 2) ? M  : N;
        int gr = base + row;
        if (gr >= lim) gr = lim - 1;
        const void* gp = src + (size_t)gr * Kld + (k0 + seg * 8);
        uint32_t sa = sbase + (uint32_t)(arr * TILE_BYTES + row * LDSB + seg * 16);
        cp_async16(sa, gp);
    }
}

// outMode: 0 = fp32 store, 1 = fp32 atomicAdd, 2 = split-bf16 store to dhi/dlo
__global__ __launch_bounds__(256)
void mma_gemm(const __nv_bfloat16* __restrict__ Ahi, const __nv_bfloat16* __restrict__ Alo,
              const __nv_bfloat16* __restrict__ Bhi, const __nv_bfloat16* __restrict__ Blo,
              float* __restrict__ C, __nv_bfloat16* __restrict__ dhi,
              __nv_bfloat16* __restrict__ dlo,
              int M, int N, int ldc, int Kld, int nStg, int outMode, int nPass)
{
    extern __shared__ char dsm[];
    const uint32_t smem = smem_u32(dsm);
    const int tid = threadIdx.x;
    const int wid = tid >> 5, lane = tid & 31;
    const int bm = blockIdx.y * 128;
    const int bn = blockIdx.x * 128;
    const int kbase = blockIdx.z * nStg * 32;

    const int wm = (wid & 1) * 64;
    const int wn = (wid >> 1) * 32;
    const int r16 = lane & 15, hkA = (lane >> 4) * 8;
    const int r8  = lane & 7,  hkB = ((lane >> 3) & 1) * 8;

    float acc[4][4][4];
#pragma unroll
    for (int i = 0; i < 4; i++)
#pragma unroll
        for (int j = 0; j < 4; j++)
#pragma unroll
            for (int q = 0; q < 4; q++) acc[i][j][q] = 0.f;

    // prefetch stages 0 and 1
    stage_load(smem, Ahi, Alo, Bhi, Blo, bm, bn, M, N, Kld, kbase, tid, nPass);
    asm volatile("cp.async.commit_group;" ::: "memory");
    if (nStg > 1) {
        stage_load(smem + STG_BYTES, Ahi, Alo, Bhi, Blo, bm, bn, M, N, Kld,
                   kbase + 32, tid, nPass);
        asm volatile("cp.async.commit_group;" ::: "memory");
    }

    for (int s = 0; s < nStg; s++) {
        if (s + 1 < nStg) { asm volatile("cp.async.wait_group 1;" ::: "memory"); }
        else              { asm volatile("cp.async.wait_group 0;" ::: "memory"); }
        __syncthreads();   // sole barrier: orders compute(s-1) reads before buf reuse

        if (s + 2 < nStg) {
            stage_load(smem + ((s + 2) % 3) * STG_BYTES, Ahi, Alo, Bhi, Blo,
                       bm, bn, M, N, Kld, kbase + (s + 2) * 32, tid, nPass);
            asm volatile("cp.async.commit_group;" ::: "memory");
        }

        const uint32_t stg = smem + (s % 3) * STG_BYTES;
        const uint32_t sAh = stg;
        const uint32_t sAl = stg + TILE_BYTES;
        const uint32_t sBh = stg + 2 * TILE_BYTES;
        const uint32_t sBl = stg + 3 * TILE_BYTES;

#pragma unroll
        for (int k16 = 0; k16 < 32; k16 += 16) {
            uint32_t ah[4][4], al[4][4], bh[4][2], bl[4][2];
#pragma unroll
            for (int i = 0; i < 4; i++) {
                uint32_t ro = (uint32_t)((wm + i * 16 + r16) * LDSB + (k16 + hkA) * 2);
                ldsm_x4(ah[i], sAh + ro);
                if (nPass >= 3) ldsm_x4(al[i], sAl + ro);
            }
#pragma unroll
            for (int j = 0; j < 4; j++) {
                uint32_t ro = (uint32_t)((wn + j * 8 + r8) * LDSB + (k16 + hkB) * 2);
                ldsm_x2(bh[j], sBh + ro);
                if (nPass >= 2) ldsm_x2(bl[j], sBl + ro);
            }
#pragma unroll
            for (int i = 0; i < 4; i++)
#pragma unroll
                for (int j = 0; j < 4; j++) {
                    mma_bf16(acc[i][j], ah[i], bh[j]);
                    if (nPass >= 2) mma_bf16(acc[i][j], ah[i], bl[j]);
                    if (nPass >= 3) mma_bf16(acc[i][j], al[i], bh[j]);
                }
        }
    }

    const int g = lane >> 2, t4 = lane & 3;
#pragma unroll
    for (int i = 0; i < 4; i++) {
        int r0 = bm + wm + i * 16 + g;
        int r1 = r0 + 8;
#pragma unroll
        for (int j = 0; j < 4; j++) {
            int c0 = bn + wn + j * 8 + t4 * 2;
            if (outMode == 2) {
#pragma unroll
                for (int q = 0; q < 4; q++) {
                    int rr = (q < 2) ? r0 : r1;
                    int cc = c0 + (q & 1);
                    if (rr < M && cc < ldc) {
                        float v = (cc < N) ? acc[i][j][q] : 0.f;
                        __nv_bfloat16 h = __float2bfloat16(v);
                        size_t o = (size_t)rr * ldc + cc;
                        dhi[o] = h;
                        dlo[o] = __float2bfloat16(v - __bfloat162float(h));
                    }
                }
            } else if (outMode == 1) {
                if (r0 < M && c0 < N)     atomicAdd(&C[(size_t)r0 * ldc + c0],     acc[i][j][0]);
                if (r0 < M && c0 + 1 < N) atomicAdd(&C[(size_t)r0 * ldc + c0 + 1], acc[i][j][1]);
                if (r1 < M && c0 < N)     atomicAdd(&C[(size_t)r1 * ldc + c0],     acc[i][j][2]);
                if (r1 < M && c0 + 1 < N) atomicAdd(&C[(size_t)r1 * ldc + c0 + 1], acc[i][j][3]);
            } else {
                if (r0 < M && c0 < N)     C[(size_t)r0 * ldc + c0]     = acc[i][j][0];
                if (r0 < M && c0 + 1 < N) C[(size_t)r0 * ldc + c0 + 1] = acc[i][j][1];
                if (r1 < M && c0 < N)     C[(size_t)r1 * ldc + c0]     = acc[i][j][2];
                if (r1 < M && c0 + 1 < N) C[(size_t)r1 * ldc + c0 + 1] = acc[i][j][3];
            }
        }
    }
}

// =================== TN GEMM (Gram): C[j,k] = sum_b V[b,j] V[b,k] =============
#define TN_PITCH 272
#define TN_TILE  (32 * TN_PITCH)
#define TN_STG   (4 * TN_TILE)
#define TN_SMEM  (3 * TN_STG)            // 104448

__device__ __forceinline__ void stage_load_tn(
    uint32_t sbase,
    const __nv_bfloat16* __restrict__ Vhi, const __nv_bfloat16* __restrict__ Vlo,
    int bm, int bn, int Kld, int k0, int tid)
{
#pragma unroll
    for (int t = 0; t < 8; t++) {
        int idx = tid + t * 256;
        int arr = idx >> 9;
        int c   = idx & 511;
        int row = c >> 4, seg = c & 15;
        const __nv_bfloat16* src = (arr == 0 || arr == 2) ? Vhi : Vlo;
        int base = (arr < 2) ? bm : bn;
        const void* gp = src + (size_t)(k0 + row) * Kld + base + seg * 8;
        uint32_t sa = sbase + (uint32_t)(arr * TN_TILE + row * TN_PITCH + seg * 16);
        cp_async16(sa, gp);
    }
}

__global__ __launch_bounds__(256)
void mma_gemm_tn(const __nv_bfloat16* __restrict__ Vhi, const __nv_bfloat16* __restrict__ Vlo,
                 float* __restrict__ C, int MN, int ldc, int Kld, int nStg)
{
    extern __shared__ char dsm[];
    const uint32_t smem = smem_u32(dsm);
    const int tid = threadIdx.x;
    const int wid = tid >> 5, lane = tid & 31;
    const int bm = blockIdx.y * 128;
    const int bn = blockIdx.x * 128;
    const int kbase = blockIdx.z * nStg * 32;

    const int wm = (wid & 1) * 64;
    const int wn = (wid >> 1) * 32;
    const int arow = ((lane >> 4) * 8) + (lane & 7);
    const int acol = ((lane >> 3) & 1) * 8;
    const int brow = (((lane >> 3) & 1) * 8) + (lane & 7);

    float acc[4][4][4];
#pragma unroll
    for (int i = 0; i < 4; i++)
#pragma unroll
        for (int j = 0; j < 4; j++)
#pragma unroll
            for (int q = 0; q < 4; q++) acc[i][j][q] = 0.f;

    stage_load_tn(smem, Vhi, Vlo, bm, bn, Kld, kbase, tid);
    asm volatile("cp.async.commit_group;" ::: "memory");
    if (nStg > 1) {
        stage_load_tn(smem + TN_STG, Vhi, Vlo, bm, bn, Kld, kbase + 32, tid);
        asm volatile("cp.async.commit_group;" ::: "memory");
    }

    for (int s = 0; s < nStg; s++) {
        if (s + 1 < nStg) { asm volatile("cp.async.wait_group 1;" ::: "memory"); }
        else              { asm volatile("cp.async.wait_group 0;" ::: "memory"); }
        __syncthreads();

        if (s + 2 < nStg) {
            stage_load_tn(smem + ((s + 2) % 3) * TN_STG, Vhi, Vlo,
                          bm, bn, Kld, kbase + (s + 2) * 32, tid);
            asm volatile("cp.async.commit_group;" ::: "memory");
        }

        const uint32_t stg = smem + (s % 3) * TN_STG;
        const uint32_t sAh = stg;
        const uint32_t sAl = stg + TN_TILE;
        const uint32_t sBh = stg + 2 * TN_TILE;
        const uint32_t sBl = stg + 3 * TN_TILE;

#pragma unroll
        for (int k16 = 0; k16 < 32; k16 += 16) {
            uint32_t ah[4][4], al[4][4], bh[4][2], bl[4][2];
#pragma unroll
            for (int i = 0; i < 4; i++) {
                uint32_t ro = (uint32_t)((k16 + arow) * TN_PITCH + (wm + i * 16 + acol) * 2);
                ldsm_x4_t(ah[i], sAh + ro);
                ldsm_x4_t(al[i], sAl + ro);
            }
#pragma unroll
            for (int j = 0; j < 4; j++) {
                uint32_t ro = (uint32_t)((k16 + brow) * TN_PITCH + (wn + j * 8) * 2);
                ldsm_x2_t(bh[j], sBh + ro);
                ldsm_x2_t(bl[j], sBl + ro);
            }
#pragma unroll
            for (int i = 0; i < 4; i++)
#pragma unroll
                for (int j = 0; j < 4; j++) {
                    mma_bf16(acc[i][j], ah[i], bh[j]);
                    mma_bf16(acc[i][j], ah[i], bl[j]);
                    mma_bf16(acc[i][j], al[i], bh[j]);
                }
        }
    }

    const int g = lane >> 2, t4 = lane & 3;
#pragma unroll
    for (int i = 0; i < 4; i++) {
        int r0 = bm + wm + i * 16 + g;
        int r1 = r0 + 8;
#pragma unroll
        for (int j = 0; j < 4; j++) {
            int c0 = bn + wn + j * 8 + t4 * 2;
            if (r0 < MN && c0 < MN)     atomicAdd(&C[(size_t)r0 * ldc + c0],     acc[i][j][0]);
            if (r0 < MN && c0 + 1 < MN) atomicAdd(&C[(size_t)r0 * ldc + c0 + 1], acc[i][j][1]);
            if (r1 < MN && c0 < MN)     atomicAdd(&C[(size_t)r1 * ldc + c0],     acc[i][j][2]);
            if (r1 < MN && c0 + 1 < MN) atomicAdd(&C[(size_t)r1 * ldc + c0 + 1], acc[i][j][3]);
        }
    }
}

// ---------- vectorized conv ----------------------------------------------------
__global__ __launch_bounds__(256)
void conv_split_v4(const float4* __restrict__ src, uint2* __restrict__ dhi,
                   uint2* __restrict__ dlo, uint32_t total4, uint32_t kq_per_row,
                   uint32_t kq_valid, uint32_t src_q_per_row) {
    uint32_t idx = blockIdx.x * 256u + threadIdx.x;
    if (idx >= total4) return;
    uint32_t row = idx / kq_per_row;
    uint32_t kq  = idx - row * kq_per_row;
    float4 x = make_float4(0.f, 0.f, 0.f, 0.f);
    if (kq < kq_valid) x = src[(size_t)row * src_q_per_row + kq];
    __nv_bfloat16 h0 = __float2bfloat16(x.x), h1 = __float2bfloat16(x.y);
    __nv_bfloat16 h2 = __float2bfloat16(x.z), h3 = __float2bfloat16(x.w);
    __nv_bfloat16 l0 = __float2bfloat16(x.x - __bfloat162float(h0));
    __nv_bfloat16 l1 = __float2bfloat16(x.y - __bfloat162float(h1));
    __nv_bfloat16 l2 = __float2bfloat16(x.z - __bfloat162float(h2));
    __nv_bfloat16 l3 = __float2bfloat16(x.w - __bfloat162float(h3));
    uint2 hv, lv;
    hv.x = ((uint32_t)__bfloat16_as_ushort(h1) << 16) | __bfloat16_as_ushort(h0);
    hv.y = ((uint32_t)__bfloat16_as_ushort(h3) << 16) | __bfloat16_as_ushort(h2);
    lv.x = ((uint32_t)__bfloat16_as_ushort(l1) << 16) | __bfloat16_as_ushort(l0);
    lv.y = ((uint32_t)__bfloat16_as_ushort(l3) << 16) | __bfloat16_as_ushort(l2);
    size_t o = (size_t)row * kq_per_row + kq;
    dhi[o] = hv;
    dlo[o] = lv;
}

__global__ void conv_split(const float* __restrict__ src, __nv_bfloat16* __restrict__ dhi,
                           __nv_bfloat16* __restrict__ dlo, int M, int K, int Kpad) {
    uint32_t idx = blockIdx.x * blockDim.x + threadIdx.x;
    if (idx >= (uint32_t)(M * Kpad)) return;
    uint32_t k = idx % Kpad, m = idx / Kpad;
    float x = (k < (uint32_t)K) ? src[(size_t)m * K + k] : 0.f;
    __nv_bfloat16 h = __float2bfloat16(x);
    dhi[idx] = h;
    dlo[idx] = __float2bfloat16(x - __bfloat162float(h));
}

__global__ __launch_bounds__(256)
void transpose_split(const float* __restrict__ src, __nv_bfloat16* __restrict__ dhi,
                     __nv_bfloat16* __restrict__ dlo, int R, int C, int Rpad) {
    __shared__ float tile[32][33];
    int tx = threadIdx.x & 31, ty = threadIdx.x >> 5;
    int r0 = blockIdx.x * 32, c0 = blockIdx.y * 32;
#pragma unroll
    for (int j = 0; j < 32; j += 8) {
        int r = r0 + ty + j, c = c0 + tx;
        tile[ty + j][tx] = (r < R && c < C) ? src[(size_t)r * C + c] : 0.f;
    }
    __syncthreads();
#pragma unroll
    for (int j = 0; j < 32; j += 8) {
        int c = c0 + ty + j;
        int r = r0 + tx;
        if (c < C && r < Rpad) {
            float x = tile[tx][ty + j];
            __nv_bfloat16 h = __float2bfloat16(x);
            dhi[(size_t)c * Rpad + r] = h;
            dlo[(size_t)c * Rpad + r] = __float2bfloat16(x - __bfloat162float(h));
        }
    }
}

// ---------- small helpers -----------------------------------------------------
__global__ void zero_kernel() {
    int idx = blockIdx.x * blockDim.x + threadIdx.x;
    if (idx < NB2 * NB2) g_G[idx] = 0.f;
    if (idx == 0) g_scalar = 0.f;
}

// warp-per-row colsum: coalesced lane-strided reads + shfl reduction
__global__ __launch_bounds__(256)
void colsum_kernel(const float* __restrict__ Map_L,
                   const float* __restrict__ Map_g) {
    int w = (blockIdx.x * 256 + threadIdx.x) >> 5;
    int lane = threadIdx.x & 31;
    if (w >= NB2 + NG2) return;
    const float* r = (w < NB2) ? (Map_L + (size_t)w * NB2)
                               : (Map_g + (size_t)(w - NB2) * NB2);
    float s = 0.f;
    for (int j = lane; j < NB2; j += 32) s += r[j];
#pragma unroll
    for (int d = 16; d > 0; d >>= 1)
        s += __shfl_xor_sync(0xFFFFFFFFu, s, d);
    if (lane == 0) {
        s -= r[299] + r[599];
        if (w < NB2) g_colL[w] = s;
        else         g_colg[w - NB2] = s;
    }
}

__global__ void scalar_kernel(const float* __restrict__ Y,
                              const float* __restrict__ Yc,
                              const float* __restrict__ Volt) {
    const int total = NB2 * NB2 + BATCH;
    int stride = gridDim.x * blockDim.x;
    float acc = 0.f;
    for (int i = blockIdx.x * blockDim.x + threadIdx.x; i < total; i += stride) {
        if (i < NB2 * NB2) {
            int j = i / NB2;
            if (j != 299 && j != 599) acc += (Y[i] + Yc[i]) * g_G[i];
        } else {
            int b = i - NB2 * NB2;
            acc += fabsf(Volt[(size_t)b * NB2 + 300]);
        }
    }
    __shared__ float red[256];
    red[threadIdx.x] = acc;
    __syncthreads();
    for (int s = 128; s > 0; s >>= 1) {
        if (threadIdx.x < s) red[threadIdx.x] += red[threadIdx.x + s];
        __syncthreads();
    }
    if (threadIdx.x == 0) atomicAdd(&g_scalar, red[0]);
}

__global__ __launch_bounds__(256)
void epilogue_kernel(const float* __restrict__ Volt,  const float* __restrict__ P_Gens,
                     const float* __restrict__ P_Loads,
                     const float* __restrict__ mu_gu, const float* __restrict__ mu_gd,
                     const float* __restrict__ mu_vu, const float* __restrict__ mu_vd,
                     const float* __restrict__ mu_iu,
                     const float* __restrict__ Gen_max, const float* __restrict__ Gen_min,
                     const float* __restrict__ C_Pg,  float* __restrict__ out) {
    const int row = blockIdx.x;
    const int tid = threadIdx.x;
    const float* volt = Volt    + (size_t)row * NB2;
    const float* pg   = P_Gens  + (size_t)row * NG2;
    const float* pl   = P_Loads + (size_t)row * NB2;
    const float* gu   = mu_gu   + (size_t)row * NG2;
    const float* gd   = mu_gd   + (size_t)row * NG2;
    const float* vu   = mu_vu   + (size_t)row * N_BUS;
    const float* vd   = mu_vd   + (size_t)row * N_BUS;
    const float* iu   = mu_iu   + (size_t)row * N_LINE;
    const float* ibr  = g_Ibr   + (size_t)row * NL2;
    const float* st   = g_stat  + (size_t)row * NG2;

    float acc = 0.f;
    float mism = 0.f;
    for (int k = tid; k < NB2; k += 256) mism += pl[k] * g_colL[k];
    for (int g = tid; g < NG2; g += 256) mism -= pg[g] * g_colg[g];
    acc += (float)BATCH * mism;

    for (int g = tid; g < NG2; g += 256) {
        float p = pg[g];
        float du = p - Gen_max[g];
        float dd = Gen_min[g] - p;
        float u = gu[g], d = gd[g];
        acc += fmaxf(du, 0.f) + fmaxf(dd, 0.f)
             + (fabsf(u * du) + fabsf(d * dd)) * (1.0f / (float)N_GBUS)
             + fmaxf(-u, 0.f) + fmaxf(-d, 0.f);
        float cost = (g < N_GBUS) ? C_Pg[g] : 0.f;
        acc += fabsf(u - d + st[g] - cost);
    }

    for (int i = tid; i < N_BUS; i += 256) {
        float vr = volt[i], vi = volt[N_BUS + i];
        float vr2 = vr * vr, vi2 = vi * vi;
        float up = vr2 + vi2 - (1.06f * 1.06f);
        float dn = (0.94f * 0.94f) - vr2 + vi2;
        float u = vu[i], d = vd[i];
        acc += fmaxf(up, 0.f) + fmaxf(dn, 0.f)
             + fabsf(u * up) + fabsf(d * dn)
             + fmaxf(-u, 0.f) + fmaxf(-d, 0.f);
    }

    for (int l = tid; l < N_LINE; l += 256) {
        float a = ibr[l], b = ibr[N_LINE + l];
        float up = a * a + b * b - 1.0f;
        float m = iu[l];
        acc += fmaxf(up, 0.f) + fabsf(m * up) + fmaxf(-m, 0.f);
    }

    __shared__ float red[256];
    red[tid] = acc;
    __syncthreads();
    for (int s = 128; s > 0; s >>= 1) {
        if (tid < s) red[tid] += red[tid + s];
        __syncthreads();
    }
    if (tid == 0) out[row] = red[0] + g_scalar;
}

// ---------------- launch -----------------------------------------------------
extern "C" void kernel_launch(void* const* d_in, const int* in_sizes, int n_in,
                              void* d_out, int out_size) {
    const float* Volt    = (const float*)d_in[0];
    const float* P_Gens  = (const float*)d_in[1];
    const float* P_Loads = (const float*)d_in[2];
    const float* n_o_l_p = (const float*)d_in[3];
    const float* mu_gu   = (const float*)d_in[4];
    const float* mu_gd   = (const float*)d_in[5];
    const float* mu_vu   = (const float*)d_in[6];
    const float* mu_vd   = (const float*)d_in[7];
    const float* mu_iu   = (const float*)d_in[8];
    const float* Y       = (const float*)d_in[9];
    const float* Yconj   = (const float*)d_in[10];
    const float* Ybr     = (const float*)d_in[11];
    const float* IM      = (const float*)d_in[12];
    const float* Map_g   = (const float*)d_in[13];
    const float* Map_L   = (const float*)d_in[14];
    const float* Gen_max = (const float*)d_in[15];
    const float* Gen_min = (const float*)d_in[16];
    const float* C_Pg    = (const float*)d_in[17];
    float* out = (float*)d_out;

    __nv_bfloat16 *pAhi, *pAlo, *pPhi, *pPlo;
    __nv_bfloat16 *pYbrhi, *pYbrlo, *pIMThi, *pIMTlo, *pMghi, *pMglo, *pWhi, *pWlo;
    float *pG, *pIbr, *pStat;
    cudaGetSymbolAddress((void**)&pAhi,   g_Ahi);
    cudaGetSymbolAddress((void**)&pAlo,   g_Alo);
    cudaGetSymbolAddress((void**)&pPhi,   g_Phi);
    cudaGetSymbolAddress((void**)&pPlo,   g_Plo);
    cudaGetSymbolAddress((void**)&pYbrhi, g_Ybrhi);
    cudaGetSymbolAddress((void**)&pYbrlo, g_Ybrlo);
    cudaGetSymbolAddress((void**)&pIMThi, g_IMThi);
    cudaGetSymbolAddress((void**)&pIMTlo, g_IMTlo);
    cudaGetSymbolAddress((void**)&pMghi,  g_Mghi);
    cudaGetSymbolAddress((void**)&pMglo,  g_Mglo);
    cudaGetSymbolAddress((void**)&pWhi,   g_Whi);
    cudaGetSymbolAddress((void**)&pWlo,   g_Wlo);
    cudaGetSymbolAddress((void**)&pG,     g_G);
    cudaGetSymbolAddress((void**)&pIbr,   g_Ibr);
    cudaGetSymbolAddress((void**)&pStat,  g_stat);

    cudaFuncSetAttribute(mma_gemm,    cudaFuncAttributeMaxDynamicSharedMemorySize, SMEM_DYN);
    cudaFuncSetAttribute(mma_gemm_tn, cudaFuncAttributeMaxDynamicSharedMemorySize, TN_SMEM);

    zero_kernel<<<(NB2 * NB2 + 255) / 256, 256>>>();
    colsum_kernel<<<((NB2 + NG2) * 32 + 255) / 256, 256>>>(Map_L, Map_g);

    {
        uint32_t total4 = BATCH * (KP600 / 4);
        uint32_t grid = (total4 + 255) / 256;
        conv_split_v4<<<grid, 256>>>((const float4*)Volt,    (uint2*)pAhi, (uint2*)pAlo,
                                     total4, KP600 / 4, NB2 / 4, NB2 / 4);
        conv_split_v4<<<grid, 256>>>((const float4*)n_o_l_p, (uint2*)pPhi, (uint2*)pPlo,
                                     total4, KP600 / 4, NB2 / 4, NB2 / 4);
    }
    conv_split<<<(NL2 * KP822 + 255) / 256, 256>>>(Ybr,   pYbrhi, pYbrlo, NL2, NL2, KP822);
    conv_split<<<(NG2 * KP600 + 255) / 256, 256>>>(Map_g, pMghi,  pMglo,  NG2, NB2, KP600);
    transpose_split<<<dim3(KP822 / 32, (NB2 + 31) / 32), 256>>>(IM, pIMThi, pIMTlo, NL2, NB2, KP822);

    // W = Ybr @ IM, full 3-pass, fused split-bf16 output
    mma_gemm<<<dim3(5, 7, 1), 256, SMEM_DYN>>>(pYbrhi, pYbrlo, pIMThi, pIMTlo,
                                               nullptr, pWhi, pWlo,
                                               NL2, NB2, KP600, KP822, KP822 / 32, 2, 3);

    // Ibr = Volt @ W^T : 2-pass
    mma_gemm<<<dim3(7, BATCH / 128, 1), 256, SMEM_DYN>>>(pAhi, pAlo, pWhi, pWlo,
                                                         pIbr, nullptr, nullptr,
                                                         BATCH, NL2, NL2, KP600, KP600 / 32, 0, 2);
    // stat = n_o_l_p @ Map_g^T : 1-pass
    mma_gemm<<<dim3(2, BATCH / 128, 1), 256, SMEM_DYN>>>(pPhi, pPlo, pMghi, pMglo,
                                                         pStat, nullptr, nullptr,
                                                         BATCH, NG2, NG2, KP600, KP600 / 32, 0, 1);
    // G = Volt^T Volt : TN, 3-pass
    mma_gemm_tn<<<dim3(5, 5, 16), 256, TN_SMEM>>>(pAhi, pAlo, pG, NB2, NB2,
                                                  KP600, (BATCH / 16) / 32);

    scalar_kernel<<<512, 256>>>(Y, Yconj, Volt);
    epilogue_kernel<<<BATCH, 256>>>(Volt, P_Gens, P_Loads, mu_gu, mu_gd,
                                    mu_vu, mu_vd, mu_iu, Gen_max, Gen_min,
                                    C_Pg, out);
}

// round 12
// speedup vs baseline: 1.1286x; 1.1286x over previous
#include <cuda_runtime.h>
#include <cuda_bf16.h>
#include <cstdint>
#include <cstddef>

#define N_BUS   300
#define N_GBUS  69
#define N_LINE  411
#define NB2     600
#define NG2     138
#define NL2     822
#define BATCH   32768
#define KP600   640
#define KP822   832

// ---------------- device scratch ----------------------------------------------
__device__ __nv_bfloat16 g_Ahi[BATCH * KP600], g_Alo[BATCH * KP600];   // Volt
__device__ __nv_bfloat16 g_Phi[BATCH * KP600], g_Plo[BATCH * KP600];   // n_o_l_p
__device__ __nv_bfloat16 g_Ybrhi[NL2 * KP822], g_Ybrlo[NL2 * KP822];
__device__ __nv_bfloat16 g_IMThi[NB2 * KP822], g_IMTlo[NB2 * KP822];   // IM^T
__device__ __nv_bfloat16 g_Mghi[NG2 * KP600],  g_Mglo[NG2 * KP600];    // Map_g
__device__ __nv_bfloat16 g_Whi[NL2 * KP600],   g_Wlo[NL2 * KP600];     // W, ROW-PERMUTED
__device__ float g_G[NB2 * NB2];
__device__ float g_stat[BATCH * NG2];
__device__ float g_iupsum[BATCH];           // fused Σ_l i_up terms per batch row
__device__ float g_colL[NB2];
__device__ float g_colg[NG2];
__device__ float g_scalar;

__device__ __forceinline__ uint32_t smem_u32(const void* p) {
    uint32_t a;
    asm("{ .reg .u64 t; cvta.to.shared.u64 t, %1; cvt.u32.u64 %0, t; }"
        : "=r"(a) : "l"(p));
    return a;
}

__device__ __forceinline__ void cp_async16(uint32_t sa, const void* gp) {
    asm volatile("cp.async.cg.shared.global [%0], [%1], 16;"
                 :: "r"(sa), "l"(gp) : "memory");
}
__device__ __forceinline__ void ldsm_x4(uint32_t* r, uint32_t addr) {
    asm volatile("ldmatrix.sync.aligned.m8n8.x4.shared.b16 {%0,%1,%2,%3}, [%4];"
                 : "=r"(r[0]), "=r"(r[1]), "=r"(r[2]), "=r"(r[3]) : "r"(addr));
}
__device__ __forceinline__ void ldsm_x2(uint32_t* r, uint32_t addr) {
    asm volatile("ldmatrix.sync.aligned.m8n8.x2.shared.b16 {%0,%1}, [%2];"
                 : "=r"(r[0]), "=r"(r[1]) : "r"(addr));
}
__device__ __forceinline__ void ldsm_x4_t(uint32_t* r, uint32_t addr) {
    asm volatile("ldmatrix.sync.aligned.m8n8.x4.trans.shared.b16 {%0,%1,%2,%3}, [%4];"
                 : "=r"(r[0]), "=r"(r[1]), "=r"(r[2]), "=r"(r[3]) : "r"(addr));
}
__device__ __forceinline__ void ldsm_x2_t(uint32_t* r, uint32_t addr) {
    asm volatile("ldmatrix.sync.aligned.m8n8.x2.trans.shared.b16 {%0,%1}, [%2];"
                 : "=r"(r[0]), "=r"(r[1]) : "r"(addr));
}
__device__ __forceinline__ void mma_bf16(float* d, const uint32_t* a, const uint32_t* b) {
    asm volatile(
        "mma.sync.aligned.m16n8k16.row.col.f32.bf16.bf16.f32 "
        "{%0,%1,%2,%3}, {%4,%5,%6,%7}, {%8,%9}, {%0,%1,%2,%3};"
        : "+f"(d[0]), "+f"(d[1]), "+f"(d[2]), "+f"(d[3])
        : "r"(a[0]), "r"(a[1]), "r"(a[2]), "r"(a[3]), "r"(b[0]), "r"(b[1]));
}

// =================== NT GEMM (A row-major [M,K], B row-major [N,K]) ===========
// nPass: 3 = Ahi*Bhi + Ahi*Blo + Alo*Bhi ; 2 = + Ahi*Blo ; 1 = Ahi*Bhi only.
// Double-buffered cp.async pipeline (fastest measured structure).
#define LDSB 80
#define TILE_BYTES (128 * LDSB)
#define STG_BYTES  (4 * TILE_BYTES)
#define SMEM_DYN   (2 * STG_BYTES)

__device__ __forceinline__ void stage_load(
    uint32_t sbase,
    const __nv_bfloat16* __restrict__ Ahi, const __nv_bfloat16* __restrict__ Alo,
    const __nv_bfloat16* __restrict__ Bhi, const __nv_bfloat16* __restrict__ Blo,
    int bm, int bn, int M, int N, int Kld, int k0, int tid, int nPass)
{
#pragma unroll
    for (int t = 0; t < 8; t++) {
        int idx = tid + t * 256;
        int arr = idx >> 9;
        if ((arr == 1 && nPass < 3) || (arr == 3 && nPass < 2)) continue;
        int c   = idx & 511;
        int row = c >> 2, seg = c & 3;
        const __nv_bfloat16* src = (arr == 0) ? Ahi : (arr == 1) ? Alo
                                 : (arr == 2) ? Bhi : Blo;
        int base = (arr < 2) ? bm : bn;
        int lim  = (arr < 2) ? M  : N;
        int gr = base + row;
        if (gr >= lim) gr = lim - 1;
        const void* gp = src + (size_t)gr * Kld + (k0 + seg * 8);
        uint32_t sa = sbase + (uint32_t)(arr * TILE_BYTES + row * LDSB + seg * 16);
        cp_async16(sa, gp);
    }
}

// outMode: 0 = fp32 store, 2 = split-bf16 store PERMUTED rows (for W),
//          3 = fused i_up reduction (Ibr; requires M == BATCH, pair-adjacent W)
__global__ __launch_bounds__(256)
void mma_gemm(const __nv_bfloat16* __restrict__ Ahi, const __nv_bfloat16* __restrict__ Alo,
              const __nv_bfloat16* __restrict__ Bhi, const __nv_bfloat16* __restrict__ Blo,
              float* __restrict__ C, __nv_bfloat16* __restrict__ dhi,
              __nv_bfloat16* __restrict__ dlo,
              const float* __restrict__ mu_iu, float* __restrict__ iupsum,
              int M, int N, int ldc, int Kld, int nStg, int outMode, int nPass)
{
    extern __shared__ char dsm[];
    __shared__ float rowsum[128];
    const uint32_t smem = smem_u32(dsm);
    const int tid = threadIdx.x;
    const int wid = tid >> 5, lane = tid & 31;
    const int bm = blockIdx.y * 128;
    const int bn = blockIdx.x * 128;
    const int kbase = blockIdx.z * nStg * 32;

    if (outMode == 3 && tid < 128) rowsum[tid] = 0.f;

    const int wm = (wid & 1) * 64;
    const int wn = (wid >> 1) * 32;
    const int r16 = lane & 15, hkA = (lane >> 4) * 8;
    const int r8  = lane & 7,  hkB = ((lane >> 3) & 1) * 8;

    float acc[4][4][4];
#pragma unroll
    for (int i = 0; i < 4; i++)
#pragma unroll
        for (int j = 0; j < 4; j++)
#pragma unroll
            for (int q = 0; q < 4; q++) acc[i][j][q] = 0.f;

    stage_load(smem, Ahi, Alo, Bhi, Blo, bm, bn, M, N, Kld, kbase, tid, nPass);
    asm volatile("cp.async.commit_group;" ::: "memory");

    for (int s = 0; s < nStg; s++) {
        if (s + 1 < nStg)
            stage_load(smem + ((s + 1) & 1) * STG_BYTES, Ahi, Alo, Bhi, Blo,
                       bm, bn, M, N, Kld, kbase + (s + 1) * 32, tid, nPass);
        asm volatile("cp.async.commit_group;" ::: "memory");
        asm volatile("cp.async.wait_group 1;" ::: "memory");
        __syncthreads();

        const uint32_t stg = smem + (s & 1) * STG_BYTES;
        const uint32_t sAh = stg;
        const uint32_t sAl = stg + TILE_BYTES;
        const uint32_t sBh = stg + 2 * TILE_BYTES;
        const uint32_t sBl = stg + 3 * TILE_BYTES;

#pragma unroll
        for (int k16 = 0; k16 < 32; k16 += 16) {
            uint32_t ah[4][4], al[4][4], bh[4][2], bl[4][2];
#pragma unroll
            for (int i = 0; i < 4; i++) {
                uint32_t ro = (uint32_t)((wm + i * 16 + r16) * LDSB + (k16 + hkA) * 2);
                ldsm_x4(ah[i], sAh + ro);
                if (nPass >= 3) ldsm_x4(al[i], sAl + ro);
            }
#pragma unroll
            for (int j = 0; j < 4; j++) {
                uint32_t ro = (uint32_t)((wn + j * 8 + r8) * LDSB + (k16 + hkB) * 2);
                ldsm_x2(bh[j], sBh + ro);
                if (nPass >= 2) ldsm_x2(bl[j], sBl + ro);
            }
#pragma unroll
            for (int i = 0; i < 4; i++)
#pragma unroll
                for (int j = 0; j < 4; j++) {
                    mma_bf16(acc[i][j], ah[i], bh[j]);
                    if (nPass >= 2) mma_bf16(acc[i][j], ah[i], bl[j]);
                    if (nPass >= 3) mma_bf16(acc[i][j], al[i], bh[j]);
                }
        }
        __syncthreads();
    }

    const int g = lane >> 2, t4 = lane & 3;

    if (outMode == 3) {
        // fused i_up: cols (2l, 2l+1) = (re, im) of line l (W rows permuted).
#pragma unroll
        for (int i = 0; i < 4; i++) {
            int r0 = bm + wm + i * 16 + g;
            int r1 = r0 + 8;
            float s0 = 0.f, s1 = 0.f;
#pragma unroll
            for (int j = 0; j < 4; j++) {
                int c0 = bn + wn + j * 8 + t4 * 2;
                int l = c0 >> 1;
                if (l < N_LINE) {
                    float m0 = mu_iu[(size_t)r0 * N_LINE + l];
                    float up0 = acc[i][j][0] * acc[i][j][0]
                              + acc[i][j][1] * acc[i][j][1] - 1.f;
                    s0 += fmaxf(up0, 0.f) + fabsf(m0 * up0) + fmaxf(-m0, 0.f);
                    float m1 = mu_iu[(size_t)r1 * N_LINE + l];
                    float up1 = acc[i][j][2] * acc[i][j][2]
                              + acc[i][j][3] * acc[i][j][3] - 1.f;
                    s1 += fmaxf(up1, 0.f) + fabsf(m1 * up1) + fmaxf(-m1, 0.f);
                }
            }
            atomicAdd(&rowsum[wm + i * 16 + g],     s0);
            atomicAdd(&rowsum[wm + i * 16 + g + 8], s1);
        }
        __syncthreads();
        if (tid < 128) atomicAdd(&iupsum[bm + tid], rowsum[tid]);
        return;
    }

#pragma unroll
    for (int i = 0; i < 4; i++) {
        int r0 = bm + wm + i * 16 + g;
        int r1 = r0 + 8;
#pragma unroll
        for (int j = 0; j < 4; j++) {
            int c0 = bn + wn + j * 8 + t4 * 2;
            if (outMode == 2) {
                // split-bf16, ROW-PERMUTED so line pairs are column-adjacent:
                // row r -> slot 2r (r<411) / 2(r-411)+1. Pad cols zeroed.
#pragma unroll
                for (int q = 0; q < 4; q++) {
                    int rr = (q < 2) ? r0 : r1;
                    int cc = c0 + (q & 1);
                    if (rr < M && cc < ldc) {
                        int pr = (rr < N_LINE) ? 2 * rr : 2 * (rr - N_LINE) + 1;
                        float v = (cc < N) ? acc[i][j][q] : 0.f;
                        __nv_bfloat16 h = __float2bfloat16(v);
                        size_t o = (size_t)pr * ldc + cc;
                        dhi[o] = h;
                        dlo[o] = __float2bfloat16(v - __bfloat162float(h));
                    }
                }
            } else {
                if (r0 < M && c0 < N)     C[(size_t)r0 * ldc + c0]     = acc[i][j][0];
                if (r0 < M && c0 + 1 < N) C[(size_t)r0 * ldc + c0 + 1] = acc[i][j][1];
                if (r1 < M && c0 < N)     C[(size_t)r1 * ldc + c0]     = acc[i][j][2];
                if (r1 < M && c0 + 1 < N) C[(size_t)r1 * ldc + c0 + 1] = acc[i][j][3];
            }
        }
    }
}

// =================== TN GEMM (Gram): C[j,k] = sum_b V[b,j] V[b,k] =============
#define TN_PITCH 272
#define TN_TILE  (32 * TN_PITCH)
#define TN_STG   (4 * TN_TILE)
#define TN_SMEM  (2 * TN_STG)

__device__ __forceinline__ void stage_load_tn(
    uint32_t sbase,
    const __nv_bfloat16* __restrict__ Vhi, const __nv_bfloat16* __restrict__ Vlo,
    int bm, int bn, int Kld, int k0, int tid)
{
#pragma unroll
    for (int t = 0; t < 8; t++) {
        int idx = tid + t * 256;
        int arr = idx >> 9;
        int c   = idx & 511;
        int row = c >> 4, seg = c & 15;
        const __nv_bfloat16* src = (arr == 0 || arr == 2) ? Vhi : Vlo;
        int base = (arr < 2) ? bm : bn;
        const void* gp = src + (size_t)(k0 + row) * Kld + base + seg * 8;
        uint32_t sa = sbase + (uint32_t)(arr * TN_TILE + row * TN_PITCH + seg * 16);
        cp_async16(sa, gp);
    }
}

__global__ __launch_bounds__(256)
void mma_gemm_tn(const __nv_bfloat16* __restrict__ Vhi, const __nv_bfloat16* __restrict__ Vlo,
                 float* __restrict__ C, int MN, int ldc, int Kld, int nStg)
{
    extern __shared__ char dsm[];
    const uint32_t smem = smem_u32(dsm);
    const int tid = threadIdx.x;
    const int wid = tid >> 5, lane = tid & 31;
    const int bm = blockIdx.y * 128;
    const int bn = blockIdx.x * 128;
    const int kbase = blockIdx.z * nStg * 32;

    const int wm = (wid & 1) * 64;
    const int wn = (wid >> 1) * 32;
    const int arow = ((lane >> 4) * 8) + (lane & 7);
    const int acol = ((lane >> 3) & 1) * 8;
    const int brow = (((lane >> 3) & 1) * 8) + (lane & 7);

    float acc[4][4][4];
#pragma unroll
    for (int i = 0; i < 4; i++)
#pragma unroll
        for (int j = 0; j < 4; j++)
#pragma unroll
            for (int q = 0; q < 4; q++) acc[i][j][q] = 0.f;

    stage_load_tn(smem, Vhi, Vlo, bm, bn, Kld, kbase, tid);
    asm volatile("cp.async.commit_group;" ::: "memory");

    for (int s = 0; s < nStg; s++) {
        if (s + 1 < nStg)
            stage_load_tn(smem + ((s + 1) & 1) * TN_STG, Vhi, Vlo,
                          bm, bn, Kld, kbase + (s + 1) * 32, tid);
        asm volatile("cp.async.commit_group;" ::: "memory");
        asm volatile("cp.async.wait_group 1;" ::: "memory");
        __syncthreads();

        const uint32_t stg = smem + (s & 1) * TN_STG;
        const uint32_t sAh = stg;
        const uint32_t sAl = stg + TN_TILE;
        const uint32_t sBh = stg + 2 * TN_TILE;
        const uint32_t sBl = stg + 3 * TN_TILE;

#pragma unroll
        for (int k16 = 0; k16 < 32; k16 += 16) {
            uint32_t ah[4][4], al[4][4], bh[4][2], bl[4][2];
#pragma unroll
            for (int i = 0; i < 4; i++) {
                uint32_t ro = (uint32_t)((k16 + arow) * TN_PITCH + (wm + i * 16 + acol) * 2);
                ldsm_x4_t(ah[i], sAh + ro);
                ldsm_x4_t(al[i], sAl + ro);
            }
#pragma unroll
            for (int j = 0; j < 4; j++) {
                uint32_t ro = (uint32_t)((k16 + brow) * TN_PITCH + (wn + j * 8) * 2);
                ldsm_x2_t(bh[j], sBh + ro);
                ldsm_x2_t(bl[j], sBl + ro);
            }
#pragma unroll
            for (int i = 0; i < 4; i++)
#pragma unroll
                for (int j = 0; j < 4; j++) {
                    mma_bf16(acc[i][j], ah[i], bh[j]);
                    mma_bf16(acc[i][j], ah[i], bl[j]);
                    mma_bf16(acc[i][j], al[i], bh[j]);
                }
        }
        __syncthreads();
    }

    const int g = lane >> 2, t4 = lane & 3;
#pragma unroll
    for (int i = 0; i < 4; i++) {
        int r0 = bm + wm + i * 16 + g;
        int r1 = r0 + 8;
#pragma unroll
        for (int j = 0; j < 4; j++) {
            int c0 = bn + wn + j * 8 + t4 * 2;
            if (r0 < MN && c0 < MN)     atomicAdd(&C[(size_t)r0 * ldc + c0],     acc[i][j][0]);
            if (r0 < MN && c0 + 1 < MN) atomicAdd(&C[(size_t)r0 * ldc + c0 + 1], acc[i][j][1]);
            if (r1 < MN && c0 < MN)     atomicAdd(&C[(size_t)r1 * ldc + c0],     acc[i][j][2]);
            if (r1 < MN && c0 + 1 < MN) atomicAdd(&C[(size_t)r1 * ldc + c0 + 1], acc[i][j][3]);
        }
    }
}

// ---------- vectorized conv ----------------------------------------------------
__global__ __launch_bounds__(256)
void conv_split_v4(const float4* __restrict__ src, uint2* __restrict__ dhi,
                   uint2* __restrict__ dlo, uint32_t total4, uint32_t kq_per_row,
                   uint32_t kq_valid, uint32_t src_q_per_row) {
    uint32_t idx = blockIdx.x * 256u + threadIdx.x;
    if (idx >= total4) return;
    uint32_t row = idx / kq_per_row;
    uint32_t kq  = idx - row * kq_per_row;
    float4 x = make_float4(0.f, 0.f, 0.f, 0.f);
    if (kq < kq_valid) x = src[(size_t)row * src_q_per_row + kq];
    __nv_bfloat16 h0 = __float2bfloat16(x.x), h1 = __float2bfloat16(x.y);
    __nv_bfloat16 h2 = __float2bfloat16(x.z), h3 = __float2bfloat16(x.w);
    __nv_bfloat16 l0 = __float2bfloat16(x.x - __bfloat162float(h0));
    __nv_bfloat16 l1 = __float2bfloat16(x.y - __bfloat162float(h1));
    __nv_bfloat16 l2 = __float2bfloat16(x.z - __bfloat162float(h2));
    __nv_bfloat16 l3 = __float2bfloat16(x.w - __bfloat162float(h3));
    uint2 hv, lv;
    hv.x = ((uint32_t)__bfloat16_as_ushort(h1) << 16) | __bfloat16_as_ushort(h0);
    hv.y = ((uint32_t)__bfloat16_as_ushort(h3) << 16) | __bfloat16_as_ushort(h2);
    lv.x = ((uint32_t)__bfloat16_as_ushort(l1) << 16) | __bfloat16_as_ushort(l0);
    lv.y = ((uint32_t)__bfloat16_as_ushort(l3) << 16) | __bfloat16_as_ushort(l2);
    size_t o = (size_t)row * kq_per_row + kq;
    dhi[o] = hv;
    dlo[o] = lv;
}

__global__ void conv_split(const float* __restrict__ src, __nv_bfloat16* __restrict__ dhi,
                           __nv_bfloat16* __restrict__ dlo, int M, int K, int Kpad) {
    uint32_t idx = blockIdx.x * blockDim.x + threadIdx.x;
    if (idx >= (uint32_t)(M * Kpad)) return;
    uint32_t k = idx % Kpad, m = idx / Kpad;
    float x = (k < (uint32_t)K) ? src[(size_t)m * K + k] : 0.f;
    __nv_bfloat16 h = __float2bfloat16(x);
    dhi[idx] = h;
    dlo[idx] = __float2bfloat16(x - __bfloat162float(h));
}

__global__ __launch_bounds__(256)
void transpose_split(const float* __restrict__ src, __nv_bfloat16* __restrict__ dhi,
                     __nv_bfloat16* __restrict__ dlo, int R, int C, int Rpad) {
    __shared__ float tile[32][33];
    int tx = threadIdx.x & 31, ty = threadIdx.x >> 5;
    int r0 = blockIdx.x * 32, c0 = blockIdx.y * 32;
#pragma unroll
    for (int j = 0; j < 32; j += 8) {
        int r = r0 + ty + j, c = c0 + tx;
        tile[ty + j][tx] = (r < R && c < C) ? src[(size_t)r * C + c] : 0.f;
    }
    __syncthreads();
#pragma unroll
    for (int j = 0; j < 32; j += 8) {
        int c = c0 + ty + j;
        int r = r0 + tx;
        if (c < C && r < Rpad) {
            float x = tile[tx][ty + j];
            __nv_bfloat16 h = __float2bfloat16(x);
            dhi[(size_t)c * Rpad + r] = h;
            dlo[(size_t)c * Rpad + r] = __float2bfloat16(x - __bfloat162float(h));
        }
    }
}

// ---------- small helpers -----------------------------------------------------
__global__ void zero_kernel() {
    int idx = blockIdx.x * blockDim.x + threadIdx.x;
    if (idx < NB2 * NB2) g_G[idx] = 0.f;
    if (idx < BATCH) g_iupsum[idx] = 0.f;
    if (idx == 0) g_scalar = 0.f;
}

__global__ __launch_bounds__(256)
void colsum_kernel(const float* __restrict__ Map_L,
                   const float* __restrict__ Map_g) {
    int w = (blockIdx.x * 256 + threadIdx.x) >> 5;
    int lane = threadIdx.x & 31;
    if (w >= NB2 + NG2) return;
    const float* r = (w < NB2) ? (Map_L + (size_t)w * NB2)
                               : (Map_g + (size_t)(w - NB2) * NB2);
    float s = 0.f;
    for (int j = lane; j < NB2; j += 32) s += r[j];
#pragma unroll
    for (int d = 16; d > 0; d >>= 1)
        s += __shfl_xor_sync(0xFFFFFFFFu, s, d);
    if (lane == 0) {
        s -= r[299] + r[599];
        if (w < NB2) g_colL[w] = s;
        else         g_colg[w - NB2] = s;
    }
}

__global__ void scalar_kernel(const float* __restrict__ Y,
                              const float* __restrict__ Yc,
                              const float* __restrict__ Volt) {
    const int total = NB2 * NB2 + BATCH;
    int stride = gridDim.x * blockDim.x;
    float acc = 0.f;
    for (int i = blockIdx.x * blockDim.x + threadIdx.x; i < total; i += stride) {
        if (i < NB2 * NB2) {
            int j = i / NB2;
            if (j != 299 && j != 599) acc += (Y[i] + Yc[i]) * g_G[i];
        } else {
            int b = i - NB2 * NB2;
            acc += fabsf(Volt[(size_t)b * NB2 + 300]);
        }
    }
    __shared__ float red[256];
    red[threadIdx.x] = acc;
    __syncthreads();
    for (int s = 128; s > 0; s >>= 1) {
        if (threadIdx.x < s) red[threadIdx.x] += red[threadIdx.x + s];
        __syncthreads();
    }
    if (threadIdx.x == 0) atomicAdd(&g_scalar, red[0]);
}

__global__ __launch_bounds__(256)
void epilogue_kernel(const float* __restrict__ Volt,  const float* __restrict__ P_Gens,
                     const float* __restrict__ P_Loads,
                     const float* __restrict__ mu_gu, const float* __restrict__ mu_gd,
                     const float* __restrict__ mu_vu, const float* __restrict__ mu_vd,
                     const float* __restrict__ Gen_max, const float* __restrict__ Gen_min,
                     const float* __restrict__ C_Pg,  float* __restrict__ out) {
    const int row = blockIdx.x;
    const int tid = threadIdx.x;
    const float* volt = Volt    + (size_t)row * NB2;
    const float* pg   = P_Gens  + (size_t)row * NG2;
    const float* pl   = P_Loads + (size_t)row * NB2;
    const float* gu   = mu_gu   + (size_t)row * NG2;
    const float* gd   = mu_gd   + (size_t)row * NG2;
    const float* vu   = mu_vu   + (size_t)row * N_BUS;
    const float* vd   = mu_vd   + (size_t)row * N_BUS;
    const float* st   = g_stat  + (size_t)row * NG2;

    float acc = 0.f;
    float mism = 0.f;
    for (int k = tid; k < NB2; k += 256) mism += pl[k] * g_colL[k];
    for (int g = tid; g < NG2; g += 256) mism -= pg[g] * g_colg[g];
    acc += (float)BATCH * mism;

    for (int g = tid; g < NG2; g += 256) {
        float p = pg[g];
        float du = p - Gen_max[g];
        float dd = Gen_min[g] - p;
        float u = gu[g], d = gd[g];
        acc += fmaxf(du, 0.f) + fmaxf(dd, 0.f)
             + (fabsf(u * du) + fabsf(d * dd)) * (1.0f / (float)N_GBUS)
             + fmaxf(-u, 0.f) + fmaxf(-d, 0.f);
        float cost = (g < N_GBUS) ? C_Pg[g] : 0.f;
        acc += fabsf(u - d + st[g] - cost);
    }

    for (int i = tid; i < N_BUS; i += 256) {
        float vr = volt[i], vi = volt[N_BUS + i];
        float vr2 = vr * vr, vi2 = vi * vi;
        float up = vr2 + vi2 - (1.06f * 1.06f);
        float dn = (0.94f * 0.94f) - vr2 + vi2;
        float u = vu[i], d = vd[i];
        acc += fmaxf(up, 0.f) + fmaxf(dn, 0.f)
             + fabsf(u * up) + fabsf(d * dn)
             + fmaxf(-u, 0.f) + fmaxf(-d, 0.f);
    }

    __shared__ float red[256];
    red[tid] = acc;
    __syncthreads();
    for (int s = 128; s > 0; s >>= 1) {
        if (tid < s) red[tid] += red[tid + s];
        __syncthreads();
    }
    if (tid == 0) out[row] = red[0] + g_scalar + g_iupsum[row];
}

// ---------------- launch -----------------------------------------------------
extern "C" void kernel_launch(void* const* d_in, const int* in_sizes, int n_in,
                              void* d_out, int out_size) {
    const float* Volt    = (const float*)d_in[0];
    const float* P_Gens  = (const float*)d_in[1];
    const float* P_Loads = (const float*)d_in[2];
    const float* n_o_l_p = (const float*)d_in[3];
    const float* mu_gu   = (const float*)d_in[4];
    const float* mu_gd   = (const float*)d_in[5];
    const float* mu_vu   = (const float*)d_in[6];
    const float* mu_vd   = (const float*)d_in[7];
    const float* mu_iu   = (const float*)d_in[8];
    const float* Y       = (const float*)d_in[9];
    const float* Yconj   = (const float*)d_in[10];
    const float* Ybr     = (const float*)d_in[11];
    const float* IM      = (const float*)d_in[12];
    const float* Map_g   = (const float*)d_in[13];
    const float* Map_L   = (const float*)d_in[14];
    const float* Gen_max = (const float*)d_in[15];
    const float* Gen_min = (const float*)d_in[16];
    const float* C_Pg    = (const float*)d_in[17];
    float* out = (float*)d_out;

    __nv_bfloat16 *pAhi, *pAlo, *pPhi, *pPlo;
    __nv_bfloat16 *pYbrhi, *pYbrlo, *pIMThi, *pIMTlo, *pMghi, *pMglo, *pWhi, *pWlo;
    float *pG, *pStat, *pIup;
    cudaGetSymbolAddress((void**)&pAhi,   g_Ahi);
    cudaGetSymbolAddress((void**)&pAlo,   g_Alo);
    cudaGetSymbolAddress((void**)&pPhi,   g_Phi);
    cudaGetSymbolAddress((void**)&pPlo,   g_Plo);
    cudaGetSymbolAddress((void**)&pYbrhi, g_Ybrhi);
    cudaGetSymbolAddress((void**)&pYbrlo, g_Ybrlo);
    cudaGetSymbolAddress((void**)&pIMThi, g_IMThi);
    cudaGetSymbolAddress((void**)&pIMTlo, g_IMTlo);
    cudaGetSymbolAddress((void**)&pMghi,  g_Mghi);
    cudaGetSymbolAddress((void**)&pMglo,  g_Mglo);
    cudaGetSymbolAddress((void**)&pWhi,   g_Whi);
    cudaGetSymbolAddress((void**)&pWlo,   g_Wlo);
    cudaGetSymbolAddress((void**)&pG,     g_G);
    cudaGetSymbolAddress((void**)&pStat,  g_stat);
    cudaGetSymbolAddress((void**)&pIup,   g_iupsum);

    cudaFuncSetAttribute(mma_gemm,    cudaFuncAttributeMaxDynamicSharedMemorySize, SMEM_DYN);
    cudaFuncSetAttribute(mma_gemm_tn, cudaFuncAttributeMaxDynamicSharedMemorySize, TN_SMEM);

    zero_kernel<<<(NB2 * NB2 + 255) / 256, 256>>>();
    colsum_kernel<<<((NB2 + NG2) * 32 + 255) / 256, 256>>>(Map_L, Map_g);

    {
        uint32_t total4 = BATCH * (KP600 / 4);
        uint32_t grid = (total4 + 255) / 256;
        conv_split_v4<<<grid, 256>>>((const float4*)Volt,    (uint2*)pAhi, (uint2*)pAlo,
                                     total4, KP600 / 4, NB2 / 4, NB2 / 4);
        conv_split_v4<<<grid, 256>>>((const float4*)n_o_l_p, (uint2*)pPhi, (uint2*)pPlo,
                                     total4, KP600 / 4, NB2 / 4, NB2 / 4);
    }
    conv_split<<<(NL2 * KP822 + 255) / 256, 256>>>(Ybr,   pYbrhi, pYbrlo, NL2, NL2, KP822);
    conv_split<<<(NG2 * KP600 + 255) / 256, 256>>>(Map_g, pMghi,  pMglo,  NG2, NB2, KP600);
    transpose_split<<<dim3(KP822 / 32, (NB2 + 31) / 32), 256>>>(IM, pIMThi, pIMTlo, NL2, NB2, KP822);

    // W = Ybr @ IM, 3-pass, split-bf16 output with line-pair row permutation
    mma_gemm<<<dim3(5, 7, 1), 256, SMEM_DYN>>>(pYbrhi, pYbrlo, pIMThi, pIMTlo,
                                               nullptr, pWhi, pWlo, nullptr, nullptr,
                                               NL2, NB2, KP600, KP822, KP822 / 32, 2, 3);

    // Ibr GEMM, 2-pass, fused i_up reduction into g_iupsum (no Ibr materialized)
    mma_gemm<<<dim3(7, BATCH / 128, 1), 256, SMEM_DYN>>>(pAhi, pAlo, pWhi, pWlo,
                                                         nullptr, nullptr, nullptr,
                                                         mu_iu, pIup,
                                                         BATCH, NL2, NL2, KP600, KP600 / 32, 3, 2);
    // stat = n_o_l_p @ Map_g^T : 1-pass
    mma_gemm<<<dim3(2, BATCH / 128, 1), 256, SMEM_DYN>>>(pPhi, pPlo, pMghi, pMglo,
                                                         pStat, nullptr, nullptr,
                                                         nullptr, nullptr,
                                                         BATCH, NG2, NG2, KP600, KP600 / 32, 0, 1);
    // G = Volt^T Volt : TN, 3-pass
    mma_gemm_tn<<<dim3(5, 5, 16), 256, TN_SMEM>>>(pAhi, pAlo, pG, NB2, NB2,
                                                  KP600, (BATCH / 16) / 32);

    scalar_kernel<<<512, 256>>>(Y, Yconj, Volt);
    epilogue_kernel<<<BATCH, 256>>>(Volt, P_Gens, P_Loads, mu_gu, mu_gd,
                                    mu_vu, mu_vd, Gen_max, Gen_min,
                                    C_Pg, out);
}

// round 13
// speedup vs baseline: 1.2420x; 1.1005x over previous
#include <cuda_runtime.h>
#include <cuda_bf16.h>
#include <cstdint>
#include <cstddef>

#define N_BUS   300
#define N_GBUS  69
#define N_LINE  411
#define NB2     600
#define NG2     138
#define NL2     822
#define BATCH   32768
#define KP600   640
#define KP822   832

// ---------------- device scratch ----------------------------------------------
__device__ __nv_bfloat16 g_Ahi[BATCH * KP600], g_Alo[BATCH * KP600];   // Volt
__device__ __nv_bfloat16 g_Phi[BATCH * KP600];                          // n_o_l_p (hi only)
__device__ __nv_bfloat16 g_Ybrhi[NL2 * KP822], g_Ybrlo[NL2 * KP822];
__device__ __nv_bfloat16 g_IMThi[NB2 * KP822], g_IMTlo[NB2 * KP822];   // IM^T
__device__ __nv_bfloat16 g_Mghi[NG2 * KP600],  g_Mglo[NG2 * KP600];    // Map_g
__device__ __nv_bfloat16 g_Whi[NL2 * KP600],   g_Wlo[NL2 * KP600];     // W, ROW-PERMUTED
__device__ float g_G[NB2 * NB2];            // upper-triangle blocks valid
__device__ float g_stat[BATCH * NG2];
__device__ float g_iupsum[BATCH];
__device__ float g_colL[NB2];
__device__ float g_colg[NG2];
__device__ float g_scalar;

__device__ __forceinline__ uint32_t smem_u32(const void* p) {
    uint32_t a;
    asm("{ .reg .u64 t; cvta.to.shared.u64 t, %1; cvt.u32.u64 %0, t; }"
        : "=r"(a) : "l"(p));
    return a;
}

__device__ __forceinline__ void cp_async16(uint32_t sa, const void* gp) {
    asm volatile("cp.async.cg.shared.global [%0], [%1], 16;"
                 :: "r"(sa), "l"(gp) : "memory");
}
__device__ __forceinline__ void ldsm_x4(uint32_t* r, uint32_t addr) {
    asm volatile("ldmatrix.sync.aligned.m8n8.x4.shared.b16 {%0,%1,%2,%3}, [%4];"
                 : "=r"(r[0]), "=r"(r[1]), "=r"(r[2]), "=r"(r[3]) : "r"(addr));
}
__device__ __forceinline__ void ldsm_x2(uint32_t* r, uint32_t addr) {
    asm volatile("ldmatrix.sync.aligned.m8n8.x2.shared.b16 {%0,%1}, [%2];"
                 : "=r"(r[0]), "=r"(r[1]) : "r"(addr));
}
__device__ __forceinline__ void ldsm_x4_t(uint32_t* r, uint32_t addr) {
    asm volatile("ldmatrix.sync.aligned.m8n8.x4.trans.shared.b16 {%0,%1,%2,%3}, [%4];"
                 : "=r"(r[0]), "=r"(r[1]), "=r"(r[2]), "=r"(r[3]) : "r"(addr));
}
__device__ __forceinline__ void ldsm_x2_t(uint32_t* r, uint32_t addr) {
    asm volatile("ldmatrix.sync.aligned.m8n8.x2.trans.shared.b16 {%0,%1}, [%2];"
                 : "=r"(r[0]), "=r"(r[1]) : "r"(addr));
}
__device__ __forceinline__ void mma_bf16(float* d, const uint32_t* a, const uint32_t* b) {
    asm volatile(
        "mma.sync.aligned.m16n8k16.row.col.f32.bf16.bf16.f32 "
        "{%0,%1,%2,%3}, {%4,%5,%6,%7}, {%8,%9}, {%0,%1,%2,%3};"
        : "+f"(d[0]), "+f"(d[1]), "+f"(d[2]), "+f"(d[3])
        : "r"(a[0]), "r"(a[1]), "r"(a[2]), "r"(a[3]), "r"(b[0]), "r"(b[1]));
}

// =================== NT GEMM (A row-major [M,K], B row-major [N,K]) ===========
#define LDSB 80
#define TILE_BYTES (128 * LDSB)
#define STG_BYTES  (4 * TILE_BYTES)
#define SMEM_DYN   (2 * STG_BYTES)

__device__ __forceinline__ void stage_load(
    uint32_t sbase,
    const __nv_bfloat16* __restrict__ Ahi, const __nv_bfloat16* __restrict__ Alo,
    const __nv_bfloat16* __restrict__ Bhi, const __nv_bfloat16* __restrict__ Blo,
    int bm, int bn, int M, int N, int Kld, int k0, int tid, int nPass)
{
#pragma unroll
    for (int t = 0; t < 8; t++) {
        int idx = tid + t * 256;
        int arr = idx >> 9;
        if ((arr == 1 && nPass < 3) || (arr == 3 && nPass < 2)) continue;
        int c   = idx & 511;
        int row = c >> 2, seg = c & 3;
        const __nv_bfloat16* src = (arr == 0) ? Ahi : (arr == 1) ? Alo
                                 : (arr == 2) ? Bhi : Blo;
        int base = (arr < 2) ? bm : bn;
        int lim  = (arr < 2) ? M  : N;
        int gr = base + row;
        if (gr >= lim) gr = lim - 1;
        const void* gp = src + (size_t)gr * Kld + (k0 + seg * 8);
        uint32_t sa = sbase + (uint32_t)(arr * TILE_BYTES + row * LDSB + seg * 16);
        cp_async16(sa, gp);
    }
}

// outMode: 0 = fp32 store, 2 = split-bf16 store PERMUTED rows (for W),
//          3 = fused i_up reduction (Ibr; requires M == BATCH, pair-adjacent W)
__global__ __launch_bounds__(256)
void mma_gemm(const __nv_bfloat16* __restrict__ Ahi, const __nv_bfloat16* __restrict__ Alo,
              const __nv_bfloat16* __restrict__ Bhi, const __nv_bfloat16* __restrict__ Blo,
              float* __restrict__ C, __nv_bfloat16* __restrict__ dhi,
              __nv_bfloat16* __restrict__ dlo,
              const float* __restrict__ mu_iu, float* __restrict__ iupsum,
              int M, int N, int ldc, int Kld, int nStg, int outMode, int nPass)
{
    extern __shared__ char dsm[];
    __shared__ float rowsum[128];
    const uint32_t smem = smem_u32(dsm);
    const int tid = threadIdx.x;
    const int wid = tid >> 5, lane = tid & 31;
    const int bm = blockIdx.y * 128;
    const int bn = blockIdx.x * 128;
    const int kbase = blockIdx.z * nStg * 32;

    if (outMode == 3 && tid < 128) rowsum[tid] = 0.f;

    const int wm = (wid & 1) * 64;
    const int wn = (wid >> 1) * 32;
    const int r16 = lane & 15, hkA = (lane >> 4) * 8;
    const int r8  = lane & 7,  hkB = ((lane >> 3) & 1) * 8;

    float acc[4][4][4];
#pragma unroll
    for (int i = 0; i < 4; i++)
#pragma unroll
        for (int j = 0; j < 4; j++)
#pragma unroll
            for (int q = 0; q < 4; q++) acc[i][j][q] = 0.f;

    stage_load(smem, Ahi, Alo, Bhi, Blo, bm, bn, M, N, Kld, kbase, tid, nPass);
    asm volatile("cp.async.commit_group;" ::: "memory");

    for (int s = 0; s < nStg; s++) {
        if (s + 1 < nStg)
            stage_load(smem + ((s + 1) & 1) * STG_BYTES, Ahi, Alo, Bhi, Blo,
                       bm, bn, M, N, Kld, kbase + (s + 1) * 32, tid, nPass);
        asm volatile("cp.async.commit_group;" ::: "memory");
        asm volatile("cp.async.wait_group 1;" ::: "memory");
        __syncthreads();

        const uint32_t stg = smem + (s & 1) * STG_BYTES;
        const uint32_t sAh = stg;
        const uint32_t sAl = stg + TILE_BYTES;
        const uint32_t sBh = stg + 2 * TILE_BYTES;
        const uint32_t sBl = stg + 3 * TILE_BYTES;

#pragma unroll
        for (int k16 = 0; k16 < 32; k16 += 16) {
            uint32_t ah[4][4], al[4][4], bh[4][2], bl[4][2];
#pragma unroll
            for (int i = 0; i < 4; i++) {
                uint32_t ro = (uint32_t)((wm + i * 16 + r16) * LDSB + (k16 + hkA) * 2);
                ldsm_x4(ah[i], sAh + ro);
                if (nPass >= 3) ldsm_x4(al[i], sAl + ro);
            }
#pragma unroll
            for (int j = 0; j < 4; j++) {
                uint32_t ro = (uint32_t)((wn + j * 8 + r8) * LDSB + (k16 + hkB) * 2);
                ldsm_x2(bh[j], sBh + ro);
                if (nPass >= 2) ldsm_x2(bl[j], sBl + ro);
            }
#pragma unroll
            for (int i = 0; i < 4; i++)
#pragma unroll
                for (int j = 0; j < 4; j++) {
                    mma_bf16(acc[i][j], ah[i], bh[j]);
                    if (nPass >= 2) mma_bf16(acc[i][j], ah[i], bl[j]);
                    if (nPass >= 3) mma_bf16(acc[i][j], al[i], bh[j]);
                }
        }
        __syncthreads();
    }

    const int g = lane >> 2, t4 = lane & 3;

    if (outMode == 3) {
#pragma unroll
        for (int i = 0; i < 4; i++) {
            int r0 = bm + wm + i * 16 + g;
            int r1 = r0 + 8;
            float s0 = 0.f, s1 = 0.f;
#pragma unroll
            for (int j = 0; j < 4; j++) {
                int c0 = bn + wn + j * 8 + t4 * 2;
                int l = c0 >> 1;
                if (l < N_LINE) {
                    float m0 = mu_iu[(size_t)r0 * N_LINE + l];
                    float up0 = acc[i][j][0] * acc[i][j][0]
                              + acc[i][j][1] * acc[i][j][1] - 1.f;
                    s0 += fmaxf(up0, 0.f) + fabsf(m0 * up0) + fmaxf(-m0, 0.f);
                    float m1 = mu_iu[(size_t)r1 * N_LINE + l];
                    float up1 = acc[i][j][2] * acc[i][j][2]
                              + acc[i][j][3] * acc[i][j][3] - 1.f;
                    s1 += fmaxf(up1, 0.f) + fabsf(m1 * up1) + fmaxf(-m1, 0.f);
                }
            }
            atomicAdd(&rowsum[wm + i * 16 + g],     s0);
            atomicAdd(&rowsum[wm + i * 16 + g + 8], s1);
        }
        __syncthreads();
        if (tid < 128) atomicAdd(&iupsum[bm + tid], rowsum[tid]);
        return;
    }

#pragma unroll
    for (int i = 0; i < 4; i++) {
        int r0 = bm + wm + i * 16 + g;
        int r1 = r0 + 8;
#pragma unroll
        for (int j = 0; j < 4; j++) {
            int c0 = bn + wn + j * 8 + t4 * 2;
            if (outMode == 2) {
#pragma unroll
                for (int q = 0; q < 4; q++) {
                    int rr = (q < 2) ? r0 : r1;
                    int cc = c0 + (q & 1);
                    if (rr < M && cc < ldc) {
                        int pr = (rr < N_LINE) ? 2 * rr : 2 * (rr - N_LINE) + 1;
                        float v = (cc < N) ? acc[i][j][q] : 0.f;
                        __nv_bfloat16 h = __float2bfloat16(v);
                        size_t o = (size_t)pr * ldc + cc;
                        dhi[o] = h;
                        dlo[o] = __float2bfloat16(v - __bfloat162float(h));
                    }
                }
            } else {
                if (r0 < M && c0 < N)     C[(size_t)r0 * ldc + c0]     = acc[i][j][0];
                if (r0 < M && c0 + 1 < N) C[(size_t)r0 * ldc + c0 + 1] = acc[i][j][1];
                if (r1 < M && c0 < N)     C[(size_t)r1 * ldc + c0]     = acc[i][j][2];
                if (r1 < M && c0 + 1 < N) C[(size_t)r1 * ldc + c0 + 1] = acc[i][j][3];
            }
        }
    }
}

// ====== TN GEMM (Gram, UPPER-TRIANGLE TILES ONLY): C[j,k]=Σ_b V[b,j]V[b,k] ====
#define TN_PITCH 272
#define TN_TILE  (32 * TN_PITCH)
#define TN_STG   (4 * TN_TILE)
#define TN_SMEM  (2 * TN_STG)
#define TN_NBLK  5          // ceil(600/128)
#define TN_NTILE 15         // upper-triangular tile count

__device__ __forceinline__ void stage_load_tn(
    uint32_t sbase,
    const __nv_bfloat16* __restrict__ Vhi, const __nv_bfloat16* __restrict__ Vlo,
    int bm, int bn, int Kld, int k0, int tid)
{
#pragma unroll
    for (int t = 0; t < 8; t++) {
        int idx = tid + t * 256;
        int arr = idx >> 9;
        int c   = idx & 511;
        int row = c >> 4, seg = c & 15;
        const __nv_bfloat16* src = (arr == 0 || arr == 2) ? Vhi : Vlo;
        int base = (arr < 2) ? bm : bn;
        const void* gp = src + (size_t)(k0 + row) * Kld + base + seg * 8;
        uint32_t sa = sbase + (uint32_t)(arr * TN_TILE + row * TN_PITCH + seg * 16);
        cp_async16(sa, gp);
    }
}

__global__ __launch_bounds__(256)
void mma_gemm_tn(const __nv_bfloat16* __restrict__ Vhi, const __nv_bfloat16* __restrict__ Vlo,
                 float* __restrict__ C, int MN, int ldc, int Kld, int nStg)
{
    extern __shared__ char dsm[];
    const uint32_t smem = smem_u32(dsm);
    const int tid = threadIdx.x;
    const int wid = tid >> 5, lane = tid & 31;

    // decode upper-triangular tile index -> (row block by, col block bx), bx>=by
    int rem = blockIdx.x, by = 0;
    while (rem >= TN_NBLK - by) { rem -= TN_NBLK - by; by++; }
    const int bm = by * 128;
    const int bn = (by + rem) * 128;
    const int kbase = blockIdx.z * nStg * 32;

    const int wm = (wid & 1) * 64;
    const int wn = (wid >> 1) * 32;
    const int arow = ((lane >> 4) * 8) + (lane & 7);
    const int acol = ((lane >> 3) & 1) * 8;
    const int brow = (((lane >> 3) & 1) * 8) + (lane & 7);

    float acc[4][4][4];
#pragma unroll
    for (int i = 0; i < 4; i++)
#pragma unroll
        for (int j = 0; j < 4; j++)
#pragma unroll
            for (int q = 0; q < 4; q++) acc[i][j][q] = 0.f;

    stage_load_tn(smem, Vhi, Vlo, bm, bn, Kld, kbase, tid);
    asm volatile("cp.async.commit_group;" ::: "memory");

    for (int s = 0; s < nStg; s++) {
        if (s + 1 < nStg)
            stage_load_tn(smem + ((s + 1) & 1) * TN_STG, Vhi, Vlo,
                          bm, bn, Kld, kbase + (s + 1) * 32, tid);
        asm volatile("cp.async.commit_group;" ::: "memory");
        asm volatile("cp.async.wait_group 1;" ::: "memory");
        __syncthreads();

        const uint32_t stg = smem + (s & 1) * TN_STG;
        const uint32_t sAh = stg;
        const uint32_t sAl = stg + TN_TILE;
        const uint32_t sBh = stg + 2 * TN_TILE;
        const uint32_t sBl = stg + 3 * TN_TILE;

#pragma unroll
        for (int k16 = 0; k16 < 32; k16 += 16) {
            uint32_t ah[4][4], al[4][4], bh[4][2], bl[4][2];
#pragma unroll
            for (int i = 0; i < 4; i++) {
                uint32_t ro = (uint32_t)((k16 + arow) * TN_PITCH + (wm + i * 16 + acol) * 2);
                ldsm_x4_t(ah[i], sAh + ro);
                ldsm_x4_t(al[i], sAl + ro);
            }
#pragma unroll
            for (int j = 0; j < 4; j++) {
                uint32_t ro = (uint32_t)((k16 + brow) * TN_PITCH + (wn + j * 8) * 2);
                ldsm_x2_t(bh[j], sBh + ro);
                ldsm_x2_t(bl[j], sBl + ro);
            }
#pragma unroll
            for (int i = 0; i < 4; i++)
#pragma unroll
                for (int j = 0; j < 4; j++) {
                    mma_bf16(acc[i][j], ah[i], bh[j]);
                    mma_bf16(acc[i][j], ah[i], bl[j]);
                    mma_bf16(acc[i][j], al[i], bh[j]);
                }
        }
        __syncthreads();
    }

    const int g = lane >> 2, t4 = lane & 3;
#pragma unroll
    for (int i = 0; i < 4; i++) {
        int r0 = bm + wm + i * 16 + g;
        int r1 = r0 + 8;
#pragma unroll
        for (int j = 0; j < 4; j++) {
            int c0 = bn + wn + j * 8 + t4 * 2;
            if (r0 < MN && c0 < MN)     atomicAdd(&C[(size_t)r0 * ldc + c0],     acc[i][j][0]);
            if (r0 < MN && c0 + 1 < MN) atomicAdd(&C[(size_t)r0 * ldc + c0 + 1], acc[i][j][1]);
            if (r1 < MN && c0 < MN)     atomicAdd(&C[(size_t)r1 * ldc + c0],     acc[i][j][2]);
            if (r1 < MN && c0 + 1 < MN) atomicAdd(&C[(size_t)r1 * ldc + c0 + 1], acc[i][j][3]);
        }
    }
}

// ---------- vectorized conv (hi + lo) ------------------------------------------
__global__ __launch_bounds__(256)
void conv_split_v4(const float4* __restrict__ src, uint2* __restrict__ dhi,
                   uint2* __restrict__ dlo, uint32_t total4, uint32_t kq_per_row,
                   uint32_t kq_valid, uint32_t src_q_per_row) {
    uint32_t idx = blockIdx.x * 256u + threadIdx.x;
    if (idx >= total4) return;
    uint32_t row = idx / kq_per_row;
    uint32_t kq  = idx - row * kq_per_row;
    float4 x = make_float4(0.f, 0.f, 0.f, 0.f);
    if (kq < kq_valid) x = src[(size_t)row * src_q_per_row + kq];
    __nv_bfloat16 h0 = __float2bfloat16(x.x), h1 = __float2bfloat16(x.y);
    __nv_bfloat16 h2 = __float2bfloat16(x.z), h3 = __float2bfloat16(x.w);
    __nv_bfloat16 l0 = __float2bfloat16(x.x - __bfloat162float(h0));
    __nv_bfloat16 l1 = __float2bfloat16(x.y - __bfloat162float(h1));
    __nv_bfloat16 l2 = __float2bfloat16(x.z - __bfloat162float(h2));
    __nv_bfloat16 l3 = __float2bfloat16(x.w - __bfloat162float(h3));
    uint2 hv, lv;
    hv.x = ((uint32_t)__bfloat16_as_ushort(h1) << 16) | __bfloat16_as_ushort(h0);
    hv.y = ((uint32_t)__bfloat16_as_ushort(h3) << 16) | __bfloat16_as_ushort(h2);
    lv.x = ((uint32_t)__bfloat16_as_ushort(l1) << 16) | __bfloat16_as_ushort(l0);
    lv.y = ((uint32_t)__bfloat16_as_ushort(l3) << 16) | __bfloat16_as_ushort(l2);
    size_t o = (size_t)row * kq_per_row + kq;
    dhi[o] = hv;
    dlo[o] = lv;
}

// ---------- hi-only conv (n_o_l_p: its GEMM is 1-pass; lo never read) ---------
__global__ __launch_bounds__(256)
void conv_hi_v4(const float4* __restrict__ src, uint2* __restrict__ dhi,
                uint32_t total4, uint32_t kq_per_row,
                uint32_t kq_valid, uint32_t src_q_per_row) {
    uint32_t idx = blockIdx.x * 256u + threadIdx.x;
    if (idx >= total4) return;
    uint32_t row = idx / kq_per_row;
    uint32_t kq  = idx - row * kq_per_row;
    float4 x = make_float4(0.f, 0.f, 0.f, 0.f);
    if (kq < kq_valid) x = src[(size_t)row * src_q_per_row + kq];
    uint2 hv;
    hv.x = ((uint32_t)__bfloat16_as_ushort(__float2bfloat16(x.y)) << 16)
         | __bfloat16_as_ushort(__float2bfloat16(x.x));
    hv.y = ((uint32_t)__bfloat16_as_ushort(__float2bfloat16(x.w)) << 16)
         | __bfloat16_as_ushort(__float2bfloat16(x.z));
    dhi[(size_t)row * kq_per_row + kq] = hv;
}

__global__ void conv_split(const float* __restrict__ src, __nv_bfloat16* __restrict__ dhi,
                           __nv_bfloat16* __restrict__ dlo, int M, int K, int Kpad) {
    uint32_t idx = blockIdx.x * blockDim.x + threadIdx.x;
    if (idx >= (uint32_t)(M * Kpad)) return;
    uint32_t k = idx % Kpad, m = idx / Kpad;
    float x = (k < (uint32_t)K) ? src[(size_t)m * K + k] : 0.f;
    __nv_bfloat16 h = __float2bfloat16(x);
    dhi[idx] = h;
    dlo[idx] = __float2bfloat16(x - __bfloat162float(h));
}

__global__ __launch_bounds__(256)
void transpose_split(const float* __restrict__ src, __nv_bfloat16* __restrict__ dhi,
                     __nv_bfloat16* __restrict__ dlo, int R, int C, int Rpad) {
    __shared__ float tile[32][33];
    int tx = threadIdx.x & 31, ty = threadIdx.x >> 5;
    int r0 = blockIdx.x * 32, c0 = blockIdx.y * 32;
#pragma unroll
    for (int j = 0; j < 32; j += 8) {
        int r = r0 + ty + j, c = c0 + tx;
        tile[ty + j][tx] = (r < R && c < C) ? src[(size_t)r * C + c] : 0.f;
    }
    __syncthreads();
#pragma unroll
    for (int j = 0; j < 32; j += 8) {
        int c = c0 + ty + j;
        int r = r0 + tx;
        if (c < C && r < Rpad) {
            float x = tile[tx][ty + j];
            __nv_bfloat16 h = __float2bfloat16(x);
            dhi[(size_t)c * Rpad + r] = h;
            dlo[(size_t)c * Rpad + r] = __float2bfloat16(x - __bfloat162float(h));
        }
    }
}

// ---------- small helpers -----------------------------------------------------
__global__ void zero_kernel() {
    int idx = blockIdx.x * blockDim.x + threadIdx.x;
    if (idx < NB2 * NB2) g_G[idx] = 0.f;
    if (idx < BATCH) g_iupsum[idx] = 0.f;
    if (idx == 0) g_scalar = 0.f;
}

__global__ __launch_bounds__(256)
void colsum_kernel(const float* __restrict__ Map_L,
                   const float* __restrict__ Map_g) {
    int w = (blockIdx.x * 256 + threadIdx.x) >> 5;
    int lane = threadIdx.x & 31;
    if (w >= NB2 + NG2) return;
    const float* r = (w < NB2) ? (Map_L + (size_t)w * NB2)
                               : (Map_g + (size_t)(w - NB2) * NB2);
    float s = 0.f;
    for (int j = lane; j < NB2; j += 32) s += r[j];
#pragma unroll
    for (int d = 16; d > 0; d >>= 1)
        s += __shfl_xor_sync(0xFFFFFFFFu, s, d);
    if (lane == 0) {
        s -= r[299] + r[599];
        if (w < NB2) g_colL[w] = s;
        else         g_colg[w - NB2] = s;
    }
}

// symmetric-weight scalar: Σ_{j<=k} w(j,k) G[j,k], G upper-triangle valid
__global__ void scalar_kernel(const float* __restrict__ Y,
                              const float* __restrict__ Yc,
                              const float* __restrict__ Volt) {
    const int total = NB2 * NB2 + BATCH;
    int stride = gridDim.x * blockDim.x;
    float acc = 0.f;
    for (int i = blockIdx.x * blockDim.x + threadIdx.x; i < total; i += stride) {
        if (i < NB2 * NB2) {
            int j = i / NB2, k = i % NB2;
            if (j <= k) {
                float w = 0.f;
                if (j != 299 && j != 599) w += Y[i] + Yc[i];
                if (j < k && k != 299 && k != 599) {
                    int t = k * NB2 + j;
                    w += Y[t] + Yc[t];
                }
                acc += w * g_G[i];
            }
        } else {
            int b = i - NB2 * NB2;
            acc += fabsf(Volt[(size_t)b * NB2 + 300]);
        }
    }
    __shared__ float red[256];
    red[threadIdx.x] = acc;
    __syncthreads();
    for (int s = 128; s > 0; s >>= 1) {
        if (threadIdx.x < s) red[threadIdx.x] += red[threadIdx.x + s];
        __syncthreads();
    }
    if (threadIdx.x == 0) atomicAdd(&g_scalar, red[0]);
}

__global__ __launch_bounds__(256)
void epilogue_kernel(const float* __restrict__ Volt,  const float* __restrict__ P_Gens,
                     const float* __restrict__ P_Loads,
                     const float* __restrict__ mu_gu, const float* __restrict__ mu_gd,
                     const float* __restrict__ mu_vu, const float* __restrict__ mu_vd,
                     const float* __restrict__ Gen_max, const float* __restrict__ Gen_min,
                     const float* __restrict__ C_Pg,  float* __restrict__ out) {
    const int row = blockIdx.x;
    const int tid = threadIdx.x;
    const float* volt = Volt    + (size_t)row * NB2;
    const float* pg   = P_Gens  + (size_t)row * NG2;
    const float* pl   = P_Loads + (size_t)row * NB2;
    const float* gu   = mu_gu   + (size_t)row * NG2;
    const float* gd   = mu_gd   + (size_t)row * NG2;
    const float* vu   = mu_vu   + (size_t)row * N_BUS;
    const float* vd   = mu_vd   + (size_t)row * N_BUS;
    const float* st   = g_stat  + (size_t)row * NG2;

    float acc = 0.f;
    float mism = 0.f;
    for (int k = tid; k < NB2; k += 256) mism += pl[k] * g_colL[k];
    for (int g = tid; g < NG2; g += 256) mism -= pg[g] * g_colg[g];
    acc += (float)BATCH * mism;

    for (int g = tid; g < NG2; g += 256) {
        float p = pg[g];
        float du = p - Gen_max[g];
        float dd = Gen_min[g] - p;
        float u = gu[g], d = gd[g];
        acc += fmaxf(du, 0.f) + fmaxf(dd, 0.f)
             + (fabsf(u * du) + fabsf(d * dd)) * (1.0f / (float)N_GBUS)
             + fmaxf(-u, 0.f) + fmaxf(-d, 0.f);
        float cost = (g < N_GBUS) ? C_Pg[g] : 0.f;
        acc += fabsf(u - d + st[g] - cost);
    }

    for (int i = tid; i < N_BUS; i += 256) {
        float vr = volt[i], vi = volt[N_BUS + i];
        float vr2 = vr * vr, vi2 = vi * vi;
        float up = vr2 + vi2 - (1.06f * 1.06f);
        float dn = (0.94f * 0.94f) - vr2 + vi2;
        float u = vu[i], d = vd[i];
        acc += fmaxf(up, 0.f) + fmaxf(dn, 0.f)
             + fabsf(u * up) + fabsf(d * dn)
             + fmaxf(-u, 0.f) + fmaxf(-d, 0.f);
    }

    __shared__ float red[256];
    red[tid] = acc;
    __syncthreads();
    for (int s = 128; s > 0; s >>= 1) {
        if (tid < s) red[tid] += red[tid + s];
        __syncthreads();
    }
    if (tid == 0) out[row] = red[0] + g_scalar + g_iupsum[row];
}

// ---------------- launch -----------------------------------------------------
extern "C" void kernel_launch(void* const* d_in, const int* in_sizes, int n_in,
                              void* d_out, int out_size) {
    const float* Volt    = (const float*)d_in[0];
    const float* P_Gens  = (const float*)d_in[1];
    const float* P_Loads = (const float*)d_in[2];
    const float* n_o_l_p = (const float*)d_in[3];
    const float* mu_gu   = (const float*)d_in[4];
    const float* mu_gd   = (const float*)d_in[5];
    const float* mu_vu   = (const float*)d_in[6];
    const float* mu_vd   = (const float*)d_in[7];
    const float* mu_iu   = (const float*)d_in[8];
    const float* Y       = (const float*)d_in[9];
    const float* Yconj   = (const float*)d_in[10];
    const float* Ybr     = (const float*)d_in[11];
    const float* IM      = (const float*)d_in[12];
    const float* Map_g   = (const float*)d_in[13];
    const float* Map_L   = (const float*)d_in[14];
    const float* Gen_max = (const float*)d_in[15];
    const float* Gen_min = (const float*)d_in[16];
    const float* C_Pg    = (const float*)d_in[17];
    float* out = (float*)d_out;

    __nv_bfloat16 *pAhi, *pAlo, *pPhi;
    __nv_bfloat16 *pYbrhi, *pYbrlo, *pIMThi, *pIMTlo, *pMghi, *pMglo, *pWhi, *pWlo;
    float *pG, *pStat, *pIup;
    cudaGetSymbolAddress((void**)&pAhi,   g_Ahi);
    cudaGetSymbolAddress((void**)&pAlo,   g_Alo);
    cudaGetSymbolAddress((void**)&pPhi,   g_Phi);
    cudaGetSymbolAddress((void**)&pYbrhi, g_Ybrhi);
    cudaGetSymbolAddress((void**)&pYbrlo, g_Ybrlo);
    cudaGetSymbolAddress((void**)&pIMThi, g_IMThi);
    cudaGetSymbolAddress((void**)&pIMTlo, g_IMTlo);
    cudaGetSymbolAddress((void**)&pMghi,  g_Mghi);
    cudaGetSymbolAddress((void**)&pMglo,  g_Mglo);
    cudaGetSymbolAddress((void**)&pWhi,   g_Whi);
    cudaGetSymbolAddress((void**)&pWlo,   g_Wlo);
    cudaGetSymbolAddress((void**)&pG,     g_G);
    cudaGetSymbolAddress((void**)&pStat,  g_stat);
    cudaGetSymbolAddress((void**)&pIup,   g_iupsum);

    cudaFuncSetAttribute(mma_gemm,    cudaFuncAttributeMaxDynamicSharedMemorySize, SMEM_DYN);
    cudaFuncSetAttribute(mma_gemm_tn, cudaFuncAttributeMaxDynamicSharedMemorySize, TN_SMEM);

    zero_kernel<<<(NB2 * NB2 + 255) / 256, 256>>>();
    colsum_kernel<<<((NB2 + NG2) * 32 + 255) / 256, 256>>>(Map_L, Map_g);

    {
        uint32_t total4 = BATCH * (KP600 / 4);
        uint32_t grid = (total4 + 255) / 256;
        conv_split_v4<<<grid, 256>>>((const float4*)Volt, (uint2*)pAhi, (uint2*)pAlo,
                                     total4, KP600 / 4, NB2 / 4, NB2 / 4);
        conv_hi_v4<<<grid, 256>>>((const float4*)n_o_l_p, (uint2*)pPhi,
                                  total4, KP600 / 4, NB2 / 4, NB2 / 4);
    }
    conv_split<<<(NL2 * KP822 + 255) / 256, 256>>>(Ybr,   pYbrhi, pYbrlo, NL2, NL2, KP822);
    conv_split<<<(NG2 * KP600 + 255) / 256, 256>>>(Map_g, pMghi,  pMglo,  NG2, NB2, KP600);
    transpose_split<<<dim3(KP822 / 32, (NB2 + 31) / 32), 256>>>(IM, pIMThi, pIMTlo, NL2, NB2, KP822);

    // W = Ybr @ IM, 3-pass, split-bf16 output with line-pair row permutation
    mma_gemm<<<dim3(5, 7, 1), 256, SMEM_DYN>>>(pYbrhi, pYbrlo, pIMThi, pIMTlo,
                                               nullptr, pWhi, pWlo, nullptr, nullptr,
                                               NL2, NB2, KP600, KP822, KP822 / 32, 2, 3);

    // Ibr GEMM, 2-pass, fused i_up reduction into g_iupsum
    mma_gemm<<<dim3(7, BATCH / 128, 1), 256, SMEM_DYN>>>(pAhi, pAlo, pWhi, pWlo,
                                                         nullptr, nullptr, nullptr,
                                                         mu_iu, pIup,
                                                         BATCH, NL2, NL2, KP600, KP600 / 32, 3, 2);
    // stat = n_o_l_p @ Map_g^T : 1-pass (reads Phi only)
    mma_gemm<<<dim3(2, BATCH / 128, 1), 256, SMEM_DYN>>>(pPhi, nullptr, pMghi, pMglo,
                                                         pStat, nullptr, nullptr,
                                                         nullptr, nullptr,
                                                         BATCH, NG2, NG2, KP600, KP600 / 32, 0, 1);
    // G = Volt^T Volt : TN, 3-pass, UPPER-TRIANGLE tiles only (15 of 25)
    mma_gemm_tn<<<dim3(TN_NTILE, 1, 16), 256, TN_SMEM>>>(pAhi, pAlo, pG, NB2, NB2,
                                                         KP600, (BATCH / 16) / 32);

    scalar_kernel<<<512, 256>>>(Y, Yconj, Volt);
    epilogue_kernel<<<BATCH, 256>>>(Volt, P_Gens, P_Loads, mu_gu, mu_gd,
                                    mu_vu, mu_vd, Gen_max, Gen_min,
                                    C_Pg, out);
}

// round 14
// speedup vs baseline: 1.4526x; 1.1696x over previous
#include <cuda_runtime.h>
#include <cuda_bf16.h>
#include <cstdint>
#include <cstddef>

#define N_BUS   300
#define N_GBUS  69
#define N_LINE  411
#define NB2     600
#define NG2     138
#define NL2     822
#define BATCH   32768
#define KP600   640
#define KP822   832

// ---------------- device scratch ----------------------------------------------
__device__ __nv_bfloat16 g_Ahi[BATCH * KP600], g_Alo[BATCH * KP600];   // Volt
__device__ __nv_bfloat16 g_Phi[BATCH * KP600];                          // n_o_l_p (hi only)
__device__ __nv_bfloat16 g_Ybrhi[NL2 * KP822], g_Ybrlo[NL2 * KP822];
__device__ __nv_bfloat16 g_IMThi[NB2 * KP822], g_IMTlo[NB2 * KP822];   // IM^T
__device__ __nv_bfloat16 g_Mghi[NG2 * KP600],  g_Mglo[NG2 * KP600];    // Map_g
__device__ __nv_bfloat16 g_Whi[NL2 * KP600];                            // W, ROW-PERMUTED (hi only)
__device__ float g_G[NB2 * NB2];            // upper-triangle blocks valid
__device__ float g_stat[BATCH * NG2];
__device__ float g_iupsum[BATCH];
__device__ float g_colL[NB2];
__device__ float g_colg[NG2];
__device__ float g_scalar;

__device__ __forceinline__ uint32_t smem_u32(const void* p) {
    uint32_t a;
    asm("{ .reg .u64 t; cvta.to.shared.u64 t, %1; cvt.u32.u64 %0, t; }"
        : "=r"(a) : "l"(p));
    return a;
}

__device__ __forceinline__ void cp_async16(uint32_t sa, const void* gp) {
    asm volatile("cp.async.cg.shared.global [%0], [%1], 16;"
                 :: "r"(sa), "l"(gp) : "memory");
}
__device__ __forceinline__ void ldsm_x4(uint32_t* r, uint32_t addr) {
    asm volatile("ldmatrix.sync.aligned.m8n8.x4.shared.b16 {%0,%1,%2,%3}, [%4];"
                 : "=r"(r[0]), "=r"(r[1]), "=r"(r[2]), "=r"(r[3]) : "r"(addr));
}
__device__ __forceinline__ void ldsm_x2(uint32_t* r, uint32_t addr) {
    asm volatile("ldmatrix.sync.aligned.m8n8.x2.shared.b16 {%0,%1}, [%2];"
                 : "=r"(r[0]), "=r"(r[1]) : "r"(addr));
}
__device__ __forceinline__ void ldsm_x4_t(uint32_t* r, uint32_t addr) {
    asm volatile("ldmatrix.sync.aligned.m8n8.x4.trans.shared.b16 {%0,%1,%2,%3}, [%4];"
                 : "=r"(r[0]), "=r"(r[1]), "=r"(r[2]), "=r"(r[3]) : "r"(addr));
}
__device__ __forceinline__ void ldsm_x2_t(uint32_t* r, uint32_t addr) {
    asm volatile("ldmatrix.sync.aligned.m8n8.x2.trans.shared.b16 {%0,%1}, [%2];"
                 : "=r"(r[0]), "=r"(r[1]) : "r"(addr));
}
__device__ __forceinline__ void mma_bf16(float* d, const uint32_t* a, const uint32_t* b) {
    asm volatile(
        "mma.sync.aligned.m16n8k16.row.col.f32.bf16.bf16.f32 "
        "{%0,%1,%2,%3}, {%4,%5,%6,%7}, {%8,%9}, {%0,%1,%2,%3};"
        : "+f"(d[0]), "+f"(d[1]), "+f"(d[2]), "+f"(d[3])
        : "r"(a[0]), "r"(a[1]), "r"(a[2]), "r"(a[3]), "r"(b[0]), "r"(b[1]));
}

// =================== NT GEMM (A row-major [M,K], B row-major [N,K]) ===========
#define LDSB 80
#define TILE_BYTES (128 * LDSB)
#define STG_BYTES  (4 * TILE_BYTES)
#define SMEM_DYN   (2 * STG_BYTES)

__device__ __forceinline__ void stage_load(
    uint32_t sbase,
    const __nv_bfloat16* __restrict__ Ahi, const __nv_bfloat16* __restrict__ Alo,
    const __nv_bfloat16* __restrict__ Bhi, const __nv_bfloat16* __restrict__ Blo,
    int bm, int bn, int M, int N, int Kld, int k0, int tid, int nPass)
{
#pragma unroll
    for (int t = 0; t < 8; t++) {
        int idx = tid + t * 256;
        int arr = idx >> 9;
        if ((arr == 1 && nPass < 3) || (arr == 3 && nPass < 2)) continue;
        int c   = idx & 511;
        int row = c >> 2, seg = c & 3;
        const __nv_bfloat16* src = (arr == 0) ? Ahi : (arr == 1) ? Alo
                                 : (arr == 2) ? Bhi : Blo;
        int base = (arr < 2) ? bm : bn;
        int lim  = (arr < 2) ? M  : N;
        int gr = base + row;
        if (gr >= lim) gr = lim - 1;
        const void* gp = src + (size_t)gr * Kld + (k0 + seg * 8);
        uint32_t sa = sbase + (uint32_t)(arr * TILE_BYTES + row * LDSB + seg * 16);
        cp_async16(sa, gp);
    }
}

// outMode: 0 = fp32 store, 2 = split-bf16 store PERMUTED rows (for W; dlo optional),
//          3 = fused i_up reduction (Ibr; requires M == BATCH, pair-adjacent W)
__global__ __launch_bounds__(256)
void mma_gemm(const __nv_bfloat16* __restrict__ Ahi, const __nv_bfloat16* __restrict__ Alo,
              const __nv_bfloat16* __restrict__ Bhi, const __nv_bfloat16* __restrict__ Blo,
              float* __restrict__ C, __nv_bfloat16* __restrict__ dhi,
              __nv_bfloat16* __restrict__ dlo,
              const float* __restrict__ mu_iu, float* __restrict__ iupsum,
              int M, int N, int ldc, int Kld, int nStg, int outMode, int nPass)
{
    extern __shared__ char dsm[];
    __shared__ float rowsum[128];
    const uint32_t smem = smem_u32(dsm);
    const int tid = threadIdx.x;
    const int wid = tid >> 5, lane = tid & 31;
    const int bm = blockIdx.y * 128;
    const int bn = blockIdx.x * 128;
    const int kbase = blockIdx.z * nStg * 32;

    if (outMode == 3 && tid < 128) rowsum[tid] = 0.f;

    const int wm = (wid & 1) * 64;
    const int wn = (wid >> 1) * 32;
    const int r16 = lane & 15, hkA = (lane >> 4) * 8;
    const int r8  = lane & 7,  hkB = ((lane >> 3) & 1) * 8;

    float acc[4][4][4];
#pragma unroll
    for (int i = 0; i < 4; i++)
#pragma unroll
        for (int j = 0; j < 4; j++)
#pragma unroll
            for (int q = 0; q < 4; q++) acc[i][j][q] = 0.f;

    stage_load(smem, Ahi, Alo, Bhi, Blo, bm, bn, M, N, Kld, kbase, tid, nPass);
    asm volatile("cp.async.commit_group;" ::: "memory");

    for (int s = 0; s < nStg; s++) {
        if (s + 1 < nStg)
            stage_load(smem + ((s + 1) & 1) * STG_BYTES, Ahi, Alo, Bhi, Blo,
                       bm, bn, M, N, Kld, kbase + (s + 1) * 32, tid, nPass);
        asm volatile("cp.async.commit_group;" ::: "memory");
        asm volatile("cp.async.wait_group 1;" ::: "memory");
        __syncthreads();

        const uint32_t stg = smem + (s & 1) * STG_BYTES;
        const uint32_t sAh = stg;
        const uint32_t sAl = stg + TILE_BYTES;
        const uint32_t sBh = stg + 2 * TILE_BYTES;
        const uint32_t sBl = stg + 3 * TILE_BYTES;

#pragma unroll
        for (int k16 = 0; k16 < 32; k16 += 16) {
            uint32_t ah[4][4], al[4][4], bh[4][2], bl[4][2];
#pragma unroll
            for (int i = 0; i < 4; i++) {
                uint32_t ro = (uint32_t)((wm + i * 16 + r16) * LDSB + (k16 + hkA) * 2);
                ldsm_x4(ah[i], sAh + ro);
                if (nPass >= 3) ldsm_x4(al[i], sAl + ro);
            }
#pragma unroll
            for (int j = 0; j < 4; j++) {
                uint32_t ro = (uint32_t)((wn + j * 8 + r8) * LDSB + (k16 + hkB) * 2);
                ldsm_x2(bh[j], sBh + ro);
                if (nPass >= 2) ldsm_x2(bl[j], sBl + ro);
            }
#pragma unroll
            for (int i = 0; i < 4; i++)
#pragma unroll
                for (int j = 0; j < 4; j++) {
                    mma_bf16(acc[i][j], ah[i], bh[j]);
                    if (nPass >= 2) mma_bf16(acc[i][j], ah[i], bl[j]);
                    if (nPass >= 3) mma_bf16(acc[i][j], al[i], bh[j]);
                }
        }
        __syncthreads();
    }

    const int g = lane >> 2, t4 = lane & 3;

    if (outMode == 3) {
#pragma unroll
        for (int i = 0; i < 4; i++) {
            int r0 = bm + wm + i * 16 + g;
            int r1 = r0 + 8;
            float s0 = 0.f, s1 = 0.f;
#pragma unroll
            for (int j = 0; j < 4; j++) {
                int c0 = bn + wn + j * 8 + t4 * 2;
                int l = c0 >> 1;
                if (l < N_LINE) {
                    float m0 = mu_iu[(size_t)r0 * N_LINE + l];
                    float up0 = acc[i][j][0] * acc[i][j][0]
                              + acc[i][j][1] * acc[i][j][1] - 1.f;
                    s0 += fmaxf(up0, 0.f) + fabsf(m0 * up0) + fmaxf(-m0, 0.f);
                    float m1 = mu_iu[(size_t)r1 * N_LINE + l];
                    float up1 = acc[i][j][2] * acc[i][j][2]
                              + acc[i][j][3] * acc[i][j][3] - 1.f;
                    s1 += fmaxf(up1, 0.f) + fabsf(m1 * up1) + fmaxf(-m1, 0.f);
                }
            }
            atomicAdd(&rowsum[wm + i * 16 + g],     s0);
            atomicAdd(&rowsum[wm + i * 16 + g + 8], s1);
        }
        __syncthreads();
        if (tid < 128) atomicAdd(&iupsum[bm + tid], rowsum[tid]);
        return;
    }

#pragma unroll
    for (int i = 0; i < 4; i++) {
        int r0 = bm + wm + i * 16 + g;
        int r1 = r0 + 8;
#pragma unroll
        for (int j = 0; j < 4; j++) {
            int c0 = bn + wn + j * 8 + t4 * 2;
            if (outMode == 2) {
#pragma unroll
                for (int q = 0; q < 4; q++) {
                    int rr = (q < 2) ? r0 : r1;
                    int cc = c0 + (q & 1);
                    if (rr < M && cc < ldc) {
                        int pr = (rr < N_LINE) ? 2 * rr : 2 * (rr - N_LINE) + 1;
                        float v = (cc < N) ? acc[i][j][q] : 0.f;
                        __nv_bfloat16 h = __float2bfloat16(v);
                        size_t o = (size_t)pr * ldc + cc;
                        dhi[o] = h;
                        if (dlo) dlo[o] = __float2bfloat16(v - __bfloat162float(h));
                    }
                }
            } else {
                if (r0 < M && c0 < N)     C[(size_t)r0 * ldc + c0]     = acc[i][j][0];
                if (r0 < M && c0 + 1 < N) C[(size_t)r0 * ldc + c0 + 1] = acc[i][j][1];
                if (r1 < M && c0 < N)     C[(size_t)r1 * ldc + c0]     = acc[i][j][2];
                if (r1 < M && c0 + 1 < N) C[(size_t)r1 * ldc + c0 + 1] = acc[i][j][3];
            }
        }
    }
}

// ====== TN GEMM (Gram, UPPER-TRIANGLE TILES ONLY): C[j,k]=Σ_b V[b,j]V[b,k] ====
#define TN_PITCH 272
#define TN_TILE  (32 * TN_PITCH)
#define TN_STG   (4 * TN_TILE)
#define TN_SMEM  (2 * TN_STG)
#define TN_NBLK  5
#define TN_NTILE 15

__device__ __forceinline__ void stage_load_tn(
    uint32_t sbase,
    const __nv_bfloat16* __restrict__ Vhi, const __nv_bfloat16* __restrict__ Vlo,
    int bm, int bn, int Kld, int k0, int tid)
{
#pragma unroll
    for (int t = 0; t < 8; t++) {
        int idx = tid + t * 256;
        int arr = idx >> 9;
        int c   = idx & 511;
        int row = c >> 4, seg = c & 15;
        const __nv_bfloat16* src = (arr == 0 || arr == 2) ? Vhi : Vlo;
        int base = (arr < 2) ? bm : bn;
        const void* gp = src + (size_t)(k0 + row) * Kld + base + seg * 8;
        uint32_t sa = sbase + (uint32_t)(arr * TN_TILE + row * TN_PITCH + seg * 16);
        cp_async16(sa, gp);
    }
}

__global__ __launch_bounds__(256)
void mma_gemm_tn(const __nv_bfloat16* __restrict__ Vhi, const __nv_bfloat16* __restrict__ Vlo,
                 float* __restrict__ C, int MN, int ldc, int Kld, int nStg)
{
    extern __shared__ char dsm[];
    const uint32_t smem = smem_u32(dsm);
    const int tid = threadIdx.x;
    const int wid = tid >> 5, lane = tid & 31;

    int rem = blockIdx.x, by = 0;
    while (rem >= TN_NBLK - by) { rem -= TN_NBLK - by; by++; }
    const int bm = by * 128;
    const int bn = (by + rem) * 128;
    const int kbase = blockIdx.z * nStg * 32;

    const int wm = (wid & 1) * 64;
    const int wn = (wid >> 1) * 32;
    const int arow = ((lane >> 4) * 8) + (lane & 7);
    const int acol = ((lane >> 3) & 1) * 8;
    const int brow = (((lane >> 3) & 1) * 8) + (lane & 7);

    float acc[4][4][4];
#pragma unroll
    for (int i = 0; i < 4; i++)
#pragma unroll
        for (int j = 0; j < 4; j++)
#pragma unroll
            for (int q = 0; q < 4; q++) acc[i][j][q] = 0.f;

    stage_load_tn(smem, Vhi, Vlo, bm, bn, Kld, kbase, tid);
    asm volatile("cp.async.commit_group;" ::: "memory");

    for (int s = 0; s < nStg; s++) {
        if (s + 1 < nStg)
            stage_load_tn(smem + ((s + 1) & 1) * TN_STG, Vhi, Vlo,
                          bm, bn, Kld, kbase + (s + 1) * 32, tid);
        asm volatile("cp.async.commit_group;" ::: "memory");
        asm volatile("cp.async.wait_group 1;" ::: "memory");
        __syncthreads();

        const uint32_t stg = smem + (s & 1) * TN_STG;
        const uint32_t sAh = stg;
        const uint32_t sAl = stg + TN_TILE;
        const uint32_t sBh = stg + 2 * TN_TILE;
        const uint32_t sBl = stg + 3 * TN_TILE;

#pragma unroll
        for (int k16 = 0; k16 < 32; k16 += 16) {
            uint32_t ah[4][4], al[4][4], bh[4][2], bl[4][2];
#pragma unroll
            for (int i = 0; i < 4; i++) {
                uint32_t ro = (uint32_t)((k16 + arow) * TN_PITCH + (wm + i * 16 + acol) * 2);
                ldsm_x4_t(ah[i], sAh + ro);
                ldsm_x4_t(al[i], sAl + ro);
            }
#pragma unroll
            for (int j = 0; j < 4; j++) {
                uint32_t ro = (uint32_t)((k16 + brow) * TN_PITCH + (wn + j * 8) * 2);
                ldsm_x2_t(bh[j], sBh + ro);
                ldsm_x2_t(bl[j], sBl + ro);
            }
#pragma unroll
            for (int i = 0; i < 4; i++)
#pragma unroll
                for (int j = 0; j < 4; j++) {
                    mma_bf16(acc[i][j], ah[i], bh[j]);
                    mma_bf16(acc[i][j], ah[i], bl[j]);
                    mma_bf16(acc[i][j], al[i], bh[j]);
                }
        }
        __syncthreads();
    }

    const int g = lane >> 2, t4 = lane & 3;
#pragma unroll
    for (int i = 0; i < 4; i++) {
        int r0 = bm + wm + i * 16 + g;
        int r1 = r0 + 8;
#pragma unroll
        for (int j = 0; j < 4; j++) {
            int c0 = bn + wn + j * 8 + t4 * 2;
            if (r0 < MN && c0 < MN)     atomicAdd(&C[(size_t)r0 * ldc + c0],     acc[i][j][0]);
            if (r0 < MN && c0 + 1 < MN) atomicAdd(&C[(size_t)r0 * ldc + c0 + 1], acc[i][j][1]);
            if (r1 < MN && c0 < MN)     atomicAdd(&C[(size_t)r1 * ldc + c0],     acc[i][j][2]);
            if (r1 < MN && c0 + 1 < MN) atomicAdd(&C[(size_t)r1 * ldc + c0 + 1], acc[i][j][3]);
        }
    }
}

// ---------- vectorized conv (hi + lo) ------------------------------------------
__global__ __launch_bounds__(256)
void conv_split_v4(const float4* __restrict__ src, uint2* __restrict__ dhi,
                   uint2* __restrict__ dlo, uint32_t total4, uint32_t kq_per_row,
                   uint32_t kq_valid, uint32_t src_q_per_row) {
    uint32_t idx = blockIdx.x * 256u + threadIdx.x;
    if (idx >= total4) return;
    uint32_t row = idx / kq_per_row;
    uint32_t kq  = idx - row * kq_per_row;
    float4 x = make_float4(0.f, 0.f, 0.f, 0.f);
    if (kq < kq_valid) x = src[(size_t)row * src_q_per_row + kq];
    __nv_bfloat16 h0 = __float2bfloat16(x.x), h1 = __float2bfloat16(x.y);
    __nv_bfloat16 h2 = __float2bfloat16(x.z), h3 = __float2bfloat16(x.w);
    __nv_bfloat16 l0 = __float2bfloat16(x.x - __bfloat162float(h0));
    __nv_bfloat16 l1 = __float2bfloat16(x.y - __bfloat162float(h1));
    __nv_bfloat16 l2 = __float2bfloat16(x.z - __bfloat162float(h2));
    __nv_bfloat16 l3 = __float2bfloat16(x.w - __bfloat162float(h3));
    uint2 hv, lv;
    hv.x = ((uint32_t)__bfloat16_as_ushort(h1) << 16) | __bfloat16_as_ushort(h0);
    hv.y = ((uint32_t)__bfloat16_as_ushort(h3) << 16) | __bfloat16_as_ushort(h2);
    lv.x = ((uint32_t)__bfloat16_as_ushort(l1) << 16) | __bfloat16_as_ushort(l0);
    lv.y = ((uint32_t)__bfloat16_as_ushort(l3) << 16) | __bfloat16_as_ushort(l2);
    size_t o = (size_t)row * kq_per_row + kq;
    dhi[o] = hv;
    dlo[o] = lv;
}

// ---------- hi-only conv -------------------------------------------------------
__global__ __launch_bounds__(256)
void conv_hi_v4(const float4* __restrict__ src, uint2* __restrict__ dhi,
                uint32_t total4, uint32_t kq_per_row,
                uint32_t kq_valid, uint32_t src_q_per_row) {
    uint32_t idx = blockIdx.x * 256u + threadIdx.x;
    if (idx >= total4) return;
    uint32_t row = idx / kq_per_row;
    uint32_t kq  = idx - row * kq_per_row;
    float4 x = make_float4(0.f, 0.f, 0.f, 0.f);
    if (kq < kq_valid) x = src[(size_t)row * src_q_per_row + kq];
    uint2 hv;
    hv.x = ((uint32_t)__bfloat16_as_ushort(__float2bfloat16(x.y)) << 16)
         | __bfloat16_as_ushort(__float2bfloat16(x.x));
    hv.y = ((uint32_t)__bfloat16_as_ushort(__float2bfloat16(x.w)) << 16)
         | __bfloat16_as_ushort(__float2bfloat16(x.z));
    dhi[(size_t)row * kq_per_row + kq] = hv;
}

__global__ void conv_split(const float* __restrict__ src, __nv_bfloat16* __restrict__ dhi,
                           __nv_bfloat16* __restrict__ dlo, int M, int K, int Kpad) {
    uint32_t idx = blockIdx.x * blockDim.x + threadIdx.x;
    if (idx >= (uint32_t)(M * Kpad)) return;
    uint32_t k = idx % Kpad, m = idx / Kpad;
    float x = (k < (uint32_t)K) ? src[(size_t)m * K + k] : 0.f;
    __nv_bfloat16 h = __float2bfloat16(x);
    dhi[idx] = h;
    dlo[idx] = __float2bfloat16(x - __bfloat162float(h));
}

__global__ __launch_bounds__(256)
void transpose_split(const float* __restrict__ src, __nv_bfloat16* __restrict__ dhi,
                     __nv_bfloat16* __restrict__ dlo, int R, int C, int Rpad) {
    __shared__ float tile[32][33];
    int tx = threadIdx.x & 31, ty = threadIdx.x >> 5;
    int r0 = blockIdx.x * 32, c0 = blockIdx.y * 32;
#pragma unroll
    for (int j = 0; j < 32; j += 8) {
        int r = r0 + ty + j, c = c0 + tx;
        tile[ty + j][tx] = (r < R && c < C) ? src[(size_t)r * C + c] : 0.f;
    }
    __syncthreads();
#pragma unroll
    for (int j = 0; j < 32; j += 8) {
        int c = c0 + ty + j;
        int r = r0 + tx;
        if (c < C && r < Rpad) {
            float x = tile[tx][ty + j];
            __nv_bfloat16 h = __float2bfloat16(x);
            dhi[(size_t)c * Rpad + r] = h;
            dlo[(size_t)c * Rpad + r] = __float2bfloat16(x - __bfloat162float(h));
        }
    }
}

// ---------- small helpers -----------------------------------------------------
__global__ void zero_kernel() {
    int idx = blockIdx.x * blockDim.x + threadIdx.x;
    if (idx < NB2 * NB2) g_G[idx] = 0.f;
    if (idx < BATCH) g_iupsum[idx] = 0.f;
    if (idx == 0) g_scalar = 0.f;
}

__global__ __launch_bounds__(256)
void colsum_kernel(const float* __restrict__ Map_L,
                   const float* __restrict__ Map_g) {
    int w = (blockIdx.x * 256 + threadIdx.x) >> 5;
    int lane = threadIdx.x & 31;
    if (w >= NB2 + NG2) return;
    const float* r = (w < NB2) ? (Map_L + (size_t)w * NB2)
                               : (Map_g + (size_t)(w - NB2) * NB2);
    float s = 0.f;
    for (int j = lane; j < NB2; j += 32) s += r[j];
#pragma unroll
    for (int d = 16; d > 0; d >>= 1)
        s += __shfl_xor_sync(0xFFFFFFFFu, s, d);
    if (lane == 0) {
        s -= r[299] + r[599];
        if (w < NB2) g_colL[w] = s;
        else         g_colg[w - NB2] = s;
    }
}

// symmetric-weight scalar: Σ_{j<=k} w(j,k) G[j,k], G upper-triangle valid
__global__ void scalar_kernel(const float* __restrict__ Y,
                              const float* __restrict__ Yc,
                              const float* __restrict__ Volt) {
    const int total = NB2 * NB2 + BATCH;
    int stride = gridDim.x * blockDim.x;
    float acc = 0.f;
    for (int i = blockIdx.x * blockDim.x + threadIdx.x; i < total; i += stride) {
        if (i < NB2 * NB2) {
            int j = i / NB2, k = i % NB2;
            if (j <= k) {
                float w = 0.f;
                if (j != 299 && j != 599) w += Y[i] + Yc[i];
                if (j < k && k != 299 && k != 599) {
                    int t = k * NB2 + j;
                    w += Y[t] + Yc[t];
                }
                acc += w * g_G[i];
            }
        } else {
            int b = i - NB2 * NB2;
            acc += fabsf(Volt[(size_t)b * NB2 + 300]);
        }
    }
    __shared__ float red[256];
    red[threadIdx.x] = acc;
    __syncthreads();
    for (int s = 128; s > 0; s >>= 1) {
        if (threadIdx.x < s) red[threadIdx.x] += red[threadIdx.x + s];
        __syncthreads();
    }
    if (threadIdx.x == 0) atomicAdd(&g_scalar, red[0]);
}

__global__ __launch_bounds__(256)
void epilogue_kernel(const float* __restrict__ Volt,  const float* __restrict__ P_Gens,
                     const float* __restrict__ P_Loads,
                     const float* __restrict__ mu_gu, const float* __restrict__ mu_gd,
                     const float* __restrict__ mu_vu, const float* __restrict__ mu_vd,
                     const float* __restrict__ Gen_max, const float* __restrict__ Gen_min,
                     const float* __restrict__ C_Pg,  float* __restrict__ out) {
    const int row = blockIdx.x;
    const int tid = threadIdx.x;
    const float* volt = Volt    + (size_t)row * NB2;
    const float* pg   = P_Gens  + (size_t)row * NG2;
    const float* pl   = P_Loads + (size_t)row * NB2;
    const float* gu   = mu_gu   + (size_t)row * NG2;
    const float* gd   = mu_gd   + (size_t)row * NG2;
    const float* vu   = mu_vu   + (size_t)row * N_BUS;
    const float* vd   = mu_vd   + (size_t)row * N_BUS;
    const float* st   = g_stat  + (size_t)row * NG2;

    float acc = 0.f;
    float mism = 0.f;
    for (int k = tid; k < NB2; k += 256) mism += pl[k] * g_colL[k];
    for (int g = tid; g < NG2; g += 256) mism -= pg[g] * g_colg[g];
    acc += (float)BATCH * mism;

    for (int g = tid; g < NG2; g += 256) {
        float p = pg[g];
        float du = p - Gen_max[g];
        float dd = Gen_min[g] - p;
        float u = gu[g], d = gd[g];
        acc += fmaxf(du, 0.f) + fmaxf(dd, 0.f)
             + (fabsf(u * du) + fabsf(d * dd)) * (1.0f / (float)N_GBUS)
             + fmaxf(-u, 0.f) + fmaxf(-d, 0.f);
        float cost = (g < N_GBUS) ? C_Pg[g] : 0.f;
        acc += fabsf(u - d + st[g] - cost);
    }

    for (int i = tid; i < N_BUS; i += 256) {
        float vr = volt[i], vi = volt[N_BUS + i];
        float vr2 = vr * vr, vi2 = vi * vi;
        float up = vr2 + vi2 - (1.06f * 1.06f);
        float dn = (0.94f * 0.94f) - vr2 + vi2;
        float u = vu[i], d = vd[i];
        acc += fmaxf(up, 0.f) + fmaxf(dn, 0.f)
             + fabsf(u * up) + fabsf(d * dn)
             + fmaxf(-u, 0.f) + fmaxf(-d, 0.f);
    }

    __shared__ float red[256];
    red[tid] = acc;
    __syncthreads();
    for (int s = 128; s > 0; s >>= 1) {
        if (tid < s) red[tid] += red[tid + s];
        __syncthreads();
    }
    if (tid == 0) out[row] = red[0] + g_scalar + g_iupsum[row];
}

// ---------------- launch -----------------------------------------------------
extern "C" void kernel_launch(void* const* d_in, const int* in_sizes, int n_in,
                              void* d_out, int out_size) {
    const float* Volt    = (const float*)d_in[0];
    const float* P_Gens  = (const float*)d_in[1];
    const float* P_Loads = (const float*)d_in[2];
    const float* n_o_l_p = (const float*)d_in[3];
    const float* mu_gu   = (const float*)d_in[4];
    const float* mu_gd   = (const float*)d_in[5];
    const float* mu_vu   = (const float*)d_in[6];
    const float* mu_vd   = (const float*)d_in[7];
    const float* mu_iu   = (const float*)d_in[8];
    const float* Y       = (const float*)d_in[9];
    const float* Yconj   = (const float*)d_in[10];
    const float* Ybr     = (const float*)d_in[11];
    const float* IM      = (const float*)d_in[12];
    const float* Map_g   = (const float*)d_in[13];
    const float* Map_L   = (const float*)d_in[14];
    const float* Gen_max = (const float*)d_in[15];
    const float* Gen_min = (const float*)d_in[16];
    const float* C_Pg    = (const float*)d_in[17];
    float* out = (float*)d_out;

    __nv_bfloat16 *pAhi, *pAlo, *pPhi;
    __nv_bfloat16 *pYbrhi, *pYbrlo, *pIMThi, *pIMTlo, *pMghi, *pMglo, *pWhi;
    float *pG, *pStat, *pIup;
    cudaGetSymbolAddress((void**)&pAhi,   g_Ahi);
    cudaGetSymbolAddress((void**)&pAlo,   g_Alo);
    cudaGetSymbolAddress((void**)&pPhi,   g_Phi);
    cudaGetSymbolAddress((void**)&pYbrhi, g_Ybrhi);
    cudaGetSymbolAddress((void**)&pYbrlo, g_Ybrlo);
    cudaGetSymbolAddress((void**)&pIMThi, g_IMThi);
    cudaGetSymbolAddress((void**)&pIMTlo, g_IMTlo);
    cudaGetSymbolAddress((void**)&pMghi,  g_Mghi);
    cudaGetSymbolAddress((void**)&pMglo,  g_Mglo);
    cudaGetSymbolAddress((void**)&pWhi,   g_Whi);
    cudaGetSymbolAddress((void**)&pG,     g_G);
    cudaGetSymbolAddress((void**)&pStat,  g_stat);
    cudaGetSymbolAddress((void**)&pIup,   g_iupsum);

    cudaFuncSetAttribute(mma_gemm,    cudaFuncAttributeMaxDynamicSharedMemorySize, SMEM_DYN);
    cudaFuncSetAttribute(mma_gemm_tn, cudaFuncAttributeMaxDynamicSharedMemorySize, TN_SMEM);

    zero_kernel<<<(NB2 * NB2 + 255) / 256, 256>>>();
    colsum_kernel<<<((NB2 + NG2) * 32 + 255) / 256, 256>>>(Map_L, Map_g);

    {
        uint32_t total4 = BATCH * (KP600 / 4);
        uint32_t grid = (total4 + 255) / 256;
        conv_split_v4<<<grid, 256>>>((const float4*)Volt, (uint2*)pAhi, (uint2*)pAlo,
                                     total4, KP600 / 4, NB2 / 4, NB2 / 4);
        conv_hi_v4<<<grid, 256>>>((const float4*)n_o_l_p, (uint2*)pPhi,
                                  total4, KP600 / 4, NB2 / 4, NB2 / 4);
    }
    conv_split<<<(NL2 * KP822 + 255) / 256, 256>>>(Ybr,   pYbrhi, pYbrlo, NL2, NL2, KP822);
    conv_split<<<(NG2 * KP600 + 255) / 256, 256>>>(Map_g, pMghi,  pMglo,  NG2, NB2, KP600);
    transpose_split<<<dim3(KP822 / 32, (NB2 + 31) / 32), 256>>>(IM, pIMThi, pIMTlo, NL2, NB2, KP822);

    // W = Ybr @ IM, 3-pass, bf16-hi output with line-pair row permutation
    mma_gemm<<<dim3(5, 7, 1), 256, SMEM_DYN>>>(pYbrhi, pYbrlo, pIMThi, pIMTlo,
                                               nullptr, pWhi, nullptr, nullptr, nullptr,
                                               NL2, NB2, KP600, KP822, KP822 / 32, 2, 3);

    // Ibr GEMM: 1-PASS (Ahi*Whi), fused i_up reduction into g_iupsum
    mma_gemm<<<dim3(7, BATCH / 128, 1), 256, SMEM_DYN>>>(pAhi, nullptr, pWhi, nullptr,
                                                         nullptr, nullptr, nullptr,
                                                         mu_iu, pIup,
                                                         BATCH, NL2, NL2, KP600, KP600 / 32, 3, 1);
    // stat = n_o_l_p @ Map_g^T : 1-pass
    mma_gemm<<<dim3(2, BATCH / 128, 1), 256, SMEM_DYN>>>(pPhi, nullptr, pMghi, pMglo,
                                                         pStat, nullptr, nullptr,
                                                         nullptr, nullptr,
                                                         BATCH, NG2, NG2, KP600, KP600 / 32, 0, 1);
    // G = Volt^T Volt : TN, 3-pass, UPPER-TRIANGLE tiles only (15 of 25)
    mma_gemm_tn<<<dim3(TN_NTILE, 1, 16), 256, TN_SMEM>>>(pAhi, pAlo, pG, NB2, NB2,
                                                         KP600, (BATCH / 16) / 32);

    scalar_kernel<<<512, 256>>>(Y, Yconj, Volt);
    epilogue_kernel<<<BATCH, 256>>>(Volt, P_Gens, P_Loads, mu_gu, mu_gd,
                                    mu_vu, mu_vd, Gen_max, Gen_min,
                                    C_Pg, out);
}